// round 7
// baseline (speedup 1.0000x reference)
#include <cuda_runtime.h>
#include <cuda_bf16.h>
#include <math_constants.h>
#include <cstdint>

#define NTOK   4096
#define DMODEL 768
#define NH     12
#define HD     64
#define KSEL   16
#define MDB    32768
#define NCH    8
#define CHUNK  (MDB/NCH)   /* 4096 keys per chunk */
#define DFF    3072
#define NCAND  32          /* rescored candidates per token */

// ---------------- scratch (device globals; no allocation allowed) ----------
__device__ float g_ln  [NTOK*DMODEL];
__device__ float g_q   [NTOK*DMODEL];
__device__ float g_attn[NTOK*DMODEL];
__device__ float g_h   [NTOK*DMODEL];
__device__ float g_ff1 [NTOK*DFF];
__device__ __nv_bfloat16 g_qb[NTOK*DMODEL];
__device__ __nv_bfloat16 g_kb[MDB*DMODEL];
__device__ uint32_t g_part[NTOK*NCH*KSEL];   // packed (ord16<<16 | 4095-lidx)
__device__ int   g_cand  [NTOK*NCAND];
__device__ int   g_topk  [NTOK*KSEL];

// ---------------- helpers ---------------------------------------------------
__device__ __forceinline__ uint32_t smem_u32(const void* p) {
    uint32_t a;
    asm("{ .reg .u64 t; cvta.to.shared.u64 t, %1; cvt.u32.u64 %0, t; }" : "=r"(a) : "l"(p));
    return a;
}

__device__ __forceinline__ void ldsm_x4(uint32_t& r0, uint32_t& r1,
                                        uint32_t& r2, uint32_t& r3, uint32_t addr) {
    asm volatile("ldmatrix.sync.aligned.m8n8.x4.shared.b16 {%0,%1,%2,%3}, [%4];"
                 : "=r"(r0), "=r"(r1), "=r"(r2), "=r"(r3) : "r"(addr));
}

__device__ __forceinline__ void mma16816(float* c, const uint32_t* a, const uint32_t* b) {
    asm("mma.sync.aligned.m16n8k16.row.col.f32.bf16.bf16.f32 "
        "{%0,%1,%2,%3}, {%4,%5,%6,%7}, {%8,%9}, {%0,%1,%2,%3};"
        : "+f"(c[0]), "+f"(c[1]), "+f"(c[2]), "+f"(c[3])
        : "r"(a[0]), "r"(a[1]), "r"(a[2]), "r"(a[3]), "r"(b[0]), "r"(b[1]));
}

__device__ __forceinline__ uint32_t f2tf32(float f) {
    uint32_t o; asm("cvt.rna.tf32.f32 %0, %1;" : "=r"(o) : "f"(f)); return o;
}

__device__ __forceinline__ void mma_tf32(float* c, const uint32_t* a, const uint32_t* b) {
    asm("mma.sync.aligned.m16n8k8.row.col.f32.tf32.tf32.f32 "
        "{%0,%1,%2,%3}, {%4,%5,%6,%7}, {%8,%9}, {%0,%1,%2,%3};"
        : "+f"(c[0]), "+f"(c[1]), "+f"(c[2]), "+f"(c[3])
        : "r"(a[0]), "r"(a[1]), "r"(a[2]), "r"(a[3]), "r"(b[0]), "r"(b[1]));
}

#define CP_ASYNC16(dst, src) \
    asm volatile("cp.async.cg.shared.global [%0], [%1], 16;" :: "r"(dst), "l"(src))
#define CP_ASYNC8(dst, src) \
    asm volatile("cp.async.ca.shared.global [%0], [%1], 8;" :: "r"(dst), "l"(src))
#define CP_COMMIT()  asm volatile("cp.async.commit_group;" ::: "memory")
#define CP_WAIT0()   asm volatile("cp.async.wait_group 0;" ::: "memory")

__device__ __forceinline__ float blockReduceSum(float v, float* red) {
    #pragma unroll
    for (int o = 16; o > 0; o >>= 1) v += __shfl_xor_sync(0xffffffffu, v, o);
    int w = threadIdx.x >> 5, l = threadIdx.x & 31;
    if (l == 0) red[w] = v;
    __syncthreads();
    if (w == 0) {
        float t = (l < 8) ? red[l] : 0.f;
        #pragma unroll
        for (int o = 4; o > 0; o >>= 1) t += __shfl_xor_sync(0xffffffffu, t, o);
        if (l == 0) red[0] = t;
    }
    __syncthreads();
    float r = red[0];
    __syncthreads();
    return r;
}

__device__ __forceinline__ float gelu_tanh(float x) {
    return 0.5f * x * (1.f + tanhf(0.7978845608028654f * (x + 0.044715f * x * x * x)));
}

__device__ __forceinline__ bool better(float s1, int i1, float s2, int i2) {
    return (s1 > s2) || (s1 == s2 && i1 < i2);
}

// pack score (bf16-order-preserving) + local idx into one sortable uint32
__device__ __forceinline__ uint32_t packkey(float s, int colLocal) {
    uint16_t b = __bfloat16_as_ushort(__float2bfloat16(s));
    uint16_t o = (b & 0x8000) ? (uint16_t)(~b) : (uint16_t)(b | 0x8000);
    return ((uint32_t)o << 16) | (uint32_t)(4095 - colLocal);
}

// half-warp insert: lanes 0-15 hold one row's sorted-desc 16-list, lanes 16-31
// another's. k uniform per half; en uniform per half. Returns nothing; caller
// refreshes threshold via shfl from local lane 15.
__device__ __forceinline__ void ins16h(uint32_t& val, uint32_t k, bool en, int lane) {
    unsigned gt = __ballot_sync(0xffffffffu, en && (k > val));
    unsigned gth = (lane < 16) ? (gt & 0xffffu) : (gt >> 16);
    uint32_t up = __shfl_up_sync(0xffffffffu, val, 1);   // local-0 never shifts
    if (gth) {
        int p = __ffs(gth) - 1;
        int loc = lane & 15;
        if (loc > p) val = up;
        if (loc == p) val = k;
    }
}

// ---------------- layernorm --------------------------------------------------
__global__ __launch_bounds__(256) void ln_kernel(
    const float* __restrict__ x, const float* __restrict__ g,
    const float* __restrict__ b, float* __restrict__ y)
{
    __shared__ float red[8];
    int row = blockIdx.x;
    const float* xr = x + (size_t)row * DMODEL;
    int t = threadIdx.x;
    float v0 = xr[t], v1 = xr[t + 256], v2 = xr[t + 512];
    float mu = blockReduceSum(v0 + v1 + v2, red) * (1.f / DMODEL);
    float d0 = v0 - mu, d1 = v1 - mu, d2 = v2 - mu;
    float var = blockReduceSum(d0 * d0 + d1 * d1 + d2 * d2, red) * (1.f / DMODEL);
    float rs = rsqrtf(var + 1e-5f);
    float* yr = y + (size_t)row * DMODEL;
    yr[t]       = d0 * rs * g[t]       + b[t];
    yr[t + 256] = d1 * rs * g[t + 256] + b[t + 256];
    yr[t + 512] = d2 * rs * g[t + 512] + b[t + 512];
}

// ---------------- combined fp32 -> bf16 convert (q then dbk) ----------------
__global__ __launch_bounds__(256) void f2bf2_kernel(
    const float* __restrict__ xq, __nv_bfloat16* __restrict__ yq,
    const float* __restrict__ xk, __nv_bfloat16* __restrict__ yk, int nq4)
{
    int i = blockIdx.x * 256 + threadIdx.x;
    const float* src; __nv_bfloat16* dst; int j;
    if (i < nq4) { src = xq; dst = yq; j = i; }
    else         { src = xk; dst = yk; j = i - nq4; }
    float4 v = reinterpret_cast<const float4*>(src)[j];
    __nv_bfloat162 a = __floats2bfloat162_rn(v.x, v.y);
    __nv_bfloat162 b = __floats2bfloat162_rn(v.z, v.w);
    reinterpret_cast<__nv_bfloat162*>(dst)[2 * j]     = a;
    reinterpret_cast<__nv_bfloat162*>(dst)[2 * j + 1] = b;
}

// ---------------- fp32 SGEMM (only used for q; preserves selection) ---------
enum { EPI_BIAS = 0, EPI_BIAS_RES = 1, EPI_GELU = 2 };

template <int EPI>
__global__ __launch_bounds__(256) void sgemm_kernel(
    const float* __restrict__ A, int lda,
    const float* __restrict__ B, int ldb,
    const float* __restrict__ bias,
    const float* __restrict__ res,
    float* __restrict__ C, int ldc, int Kd)
{
    __shared__ float As[8][128];
    __shared__ float Bs[8][128];
    int tid  = threadIdx.x;
    int brow = blockIdx.y * 128, bcol = blockIdx.x * 128;
    int arow = tid >> 1, acol = (tid & 1) * 4;
    int bkr  = tid >> 5, bcol4 = (tid & 31) * 4;
    const float* Ap = A + (size_t)(brow + arow) * lda + acol;
    const float* Bp = B + (size_t)bkr * ldb + bcol + bcol4;
    int rbase = (tid >> 4) * 4, cbase = (tid & 15) * 4;

    float acc[8][8];
    #pragma unroll
    for (int i = 0; i < 8; i++)
        #pragma unroll
        for (int j = 0; j < 8; j++) acc[i][j] = 0.f;

    for (int k0 = 0; k0 < Kd; k0 += 8) {
        float4 av = *reinterpret_cast<const float4*>(Ap + k0);
        float4 bv = *reinterpret_cast<const float4*>(Bp + (size_t)k0 * ldb);
        __syncthreads();
        As[acol + 0][arow] = av.x; As[acol + 1][arow] = av.y;
        As[acol + 2][arow] = av.z; As[acol + 3][arow] = av.w;
        *reinterpret_cast<float4*>(&Bs[bkr][bcol4]) = bv;
        __syncthreads();
        #pragma unroll
        for (int kk = 0; kk < 8; kk++) {
            float a[8], bb[8];
            *reinterpret_cast<float4*>(a)      = *reinterpret_cast<const float4*>(&As[kk][rbase]);
            *reinterpret_cast<float4*>(a + 4)  = *reinterpret_cast<const float4*>(&As[kk][rbase + 64]);
            *reinterpret_cast<float4*>(bb)     = *reinterpret_cast<const float4*>(&Bs[kk][cbase]);
            *reinterpret_cast<float4*>(bb + 4) = *reinterpret_cast<const float4*>(&Bs[kk][cbase + 64]);
            #pragma unroll
            for (int i = 0; i < 8; i++)
                #pragma unroll
                for (int j = 0; j < 8; j++) acc[i][j] += a[i] * bb[j];
        }
    }

    #pragma unroll
    for (int i = 0; i < 8; i++) {
        int r = brow + rbase + ((i < 4) ? i : 60 + i);
        #pragma unroll
        for (int jg = 0; jg < 2; jg++) {
            int c = bcol + cbase + jg * 64;
            float4 bi = *reinterpret_cast<const float4*>(bias + c);
            float4 v;
            v.x = acc[i][jg * 4 + 0] + bi.x;
            v.y = acc[i][jg * 4 + 1] + bi.y;
            v.z = acc[i][jg * 4 + 2] + bi.z;
            v.w = acc[i][jg * 4 + 3] + bi.w;
            if (EPI == EPI_BIAS_RES) {
                float4 rv = *reinterpret_cast<const float4*>(res + (size_t)r * ldc + c);
                v.x += rv.x; v.y += rv.y; v.z += rv.z; v.w += rv.w;
            } else if (EPI == EPI_GELU) {
                v.x = gelu_tanh(v.x); v.y = gelu_tanh(v.y);
                v.z = gelu_tanh(v.z); v.w = gelu_tanh(v.w);
            }
            *reinterpret_cast<float4*>(C + (size_t)r * ldc + c) = v;
        }
    }
}

// ---------------- tf32 tensor-core GEMM, cp.async double-buffered -----------
#define A_STR 20
#define B_STR 136
#define A_BUF (128 * A_STR)
#define B_BUF (16 * B_STR)

template <int EPI>
__global__ __launch_bounds__(256, 2) void tgemm_kernel(
    const float* __restrict__ A, int lda,
    const float* __restrict__ B, int ldb,
    const float* __restrict__ bias,
    const float* __restrict__ res,
    float* __restrict__ C, int ldc, int Kd)
{
    __shared__ float As[2 * A_BUF];
    __shared__ float Bs[2 * B_BUF];
    uint32_t sA = smem_u32(As), sB = smem_u32(Bs);
    int tid = threadIdx.x, lane = tid & 31, wid = tid >> 5;
    int warp_m = wid >> 2, warp_n = wid & 3;
    int brow = blockIdx.y * 128, bcol = blockIdx.x * 128;

    float acc[4][4][4];
    #pragma unroll
    for (int mt = 0; mt < 4; mt++)
        #pragma unroll
        for (int nt = 0; nt < 4; nt++)
            #pragma unroll
            for (int r = 0; r < 4; r++) acc[mt][nt][r] = 0.f;

    auto stageA = [&](int kb, int buf) {
        #pragma unroll
        for (int it = 0; it < 4; it++) {
            int c = tid + it * 256;
            int row = c >> 3, k2 = c & 7;
            uint32_t d = sA + (buf * A_BUF + row * A_STR + k2 * 2) * 4;
            const void* s = A + (size_t)(brow + row) * lda + kb + k2 * 2;
            CP_ASYNC8(d, s);
        }
    };
    auto stageB = [&](int kb, int buf) {
        #pragma unroll
        for (int it = 0; it < 2; it++) {
            int c = tid + it * 256;
            int k = c >> 5, n4 = c & 31;
            uint32_t d = sB + (buf * B_BUF + k * B_STR + n4 * 4) * 4;
            const void* s = B + (size_t)(kb + k) * ldb + bcol + n4 * 4;
            CP_ASYNC16(d, s);
        }
    };

    stageA(0, 0); stageB(0, 0); CP_COMMIT();

    int niter = Kd / 16;
    for (int i = 0; i < niter; i++) {
        CP_WAIT0();
        __syncthreads();
        if (i + 1 < niter) {
            stageA((i + 1) * 16, (i + 1) & 1);
            stageB((i + 1) * 16, (i + 1) & 1);
            CP_COMMIT();
        }
        const float* Af = As + (i & 1) * A_BUF;
        const float* Bf = Bs + (i & 1) * B_BUF;

        #pragma unroll
        for (int j = 0; j < 2; j++) {
            uint32_t a[4][4], b[4][2];
            #pragma unroll
            for (int mt = 0; mt < 4; mt++) {
                int r = warp_m * 64 + mt * 16 + (lane >> 2);
                const float* pa = Af + r * A_STR + j * 8 + (lane & 3);
                a[mt][0] = f2tf32(pa[0]);
                a[mt][1] = f2tf32(pa[8 * A_STR]);
                a[mt][2] = f2tf32(pa[4]);
                a[mt][3] = f2tf32(pa[8 * A_STR + 4]);
            }
            #pragma unroll
            for (int nt = 0; nt < 4; nt++) {
                int n = warp_n * 32 + nt * 8 + (lane >> 2);
                const float* pb = Bf + (j * 8 + (lane & 3)) * B_STR + n;
                b[nt][0] = f2tf32(pb[0]);
                b[nt][1] = f2tf32(pb[4 * B_STR]);
            }
            #pragma unroll
            for (int mt = 0; mt < 4; mt++)
                #pragma unroll
                for (int nt = 0; nt < 4; nt++)
                    mma_tf32(acc[mt][nt], a[mt], b[nt]);
        }
    }

    #pragma unroll
    for (int mt = 0; mt < 4; mt++) {
        #pragma unroll
        for (int rh = 0; rh < 2; rh++) {
            int r = brow + warp_m * 64 + mt * 16 + rh * 8 + (lane >> 2);
            #pragma unroll
            for (int nt = 0; nt < 4; nt++) {
                int c = bcol + warp_n * 32 + nt * 8 + 2 * (lane & 3);
                float2 v;
                v.x = acc[mt][nt][rh * 2 + 0] + bias[c];
                v.y = acc[mt][nt][rh * 2 + 1] + bias[c + 1];
                if (EPI == EPI_BIAS_RES) {
                    float2 rv = *reinterpret_cast<const float2*>(res + (size_t)r * ldc + c);
                    v.x += rv.x; v.y += rv.y;
                } else if (EPI == EPI_GELU) {
                    v.x = gelu_tanh(v.x); v.y = gelu_tanh(v.y);
                }
                *reinterpret_cast<float2*>(C + (size_t)r * ldc + c) = v;
            }
        }
    }
}

// ---------------- bf16 mma.sync score GEMM + register top-16 ----------------
// grid(NCH, 32); CTA = 128 q x 128 keys/kt, 4 warps (2x2), warp tile 64x64.
// smem 100352 B: buf0 A@0 B@16K; buf1 A@32K B@48K; Sc uint32[128][132] @32K.
#define SC_SC 32768

__device__ __forceinline__ void stage64_async(
    uint32_t dstb, const __nv_bfloat16* __restrict__ src, int tid)
{
    #pragma unroll
    for (int it = 0; it < 8; it++) {
        int c = tid + it * 128;          // 1024 chunks = 128 rows x 8 x 16B
        int row = c >> 3, col = c & 7;
        uint32_t d = dstb + row * 128 + ((col ^ (row & 7)) << 4);
        const void* s = src + (size_t)row * DMODEL + col * 8;
        CP_ASYNC16(d, s);
    }
}

__global__ __launch_bounds__(128, 2) void score_topk_mma(
    const __nv_bfloat16* __restrict__ qb, const __nv_bfloat16* __restrict__ kb,
    uint32_t* __restrict__ part)
{
    extern __shared__ char dsm[];
    uint32_t (*Sc)[132] = (uint32_t(*)[132])(dsm + SC_SC);
    uint32_t sbase = smem_u32(dsm);

    int tid = threadIdx.x, lane = tid & 31, wid = tid >> 5;
    int warp_m = wid >> 1, warp_n = wid & 1;
    int q0 = blockIdx.y * 128;
    int c0 = blockIdx.x * CHUNK;
    int half = lane >> 4, hl = lane & 15;

    // register top-16 lists: slot s covers rows (wid*32+2s) [lanes 0-15]
    // and (wid*32+2s+1) [lanes 16-31], each sorted desc.
    uint32_t lst[16];
    #pragma unroll
    for (int s = 0; s < 16; s++) lst[s] = 0u;

    uint32_t a_rel[4], b_rel[4];
    int a_rx[4], b_rx[4];
    #pragma unroll
    for (int mt = 0; mt < 4; mt++) {
        int row = warp_m * 64 + mt * 16 + (lane & 15);
        a_rel[mt] = row * 128;
        a_rx[mt] = row & 7;
    }
    #pragma unroll
    for (int nt4 = 0; nt4 < 4; nt4++) {
        int row = warp_n * 64 + nt4 * 16 + (lane & 7) + ((lane >> 4) << 3);
        b_rel[nt4] = row * 128;
        b_rx[nt4] = row & 7;
    }
    int a_ch = lane >> 4;
    int b_ch = (lane >> 3) & 1;

    const __nv_bfloat16* qbase = qb + (size_t)q0 * DMODEL;

    // prologue: stage kt=0 slice 0 into buf0
    stage64_async(sbase,         qbase, tid);
    stage64_async(sbase + 16384, kb + (size_t)c0 * DMODEL, tid);
    CP_COMMIT();

    for (int kt = 0; kt < CHUNK / 128; kt++) {
        int kb0 = c0 + kt * 128;
        const __nv_bfloat16* kbase = kb + (size_t)kb0 * DMODEL;

        float acc[4][8][4];
        #pragma unroll
        for (int mt = 0; mt < 4; mt++)
            #pragma unroll
            for (int n8 = 0; n8 < 8; n8++)
                #pragma unroll
                for (int r = 0; r < 4; r++) acc[mt][n8][r] = 0.f;

        for (int kc = 0; kc < DMODEL / 64; kc++) {
            CP_WAIT0();
            __syncthreads();
            if (kc + 1 < DMODEL / 64) {   // prefetch next slice of this kt
                uint32_t nb = sbase + ((kc + 1) & 1) * 32768;
                stage64_async(nb,         qbase + (kc + 1) * 64, tid);
                stage64_async(nb + 16384, kbase + (kc + 1) * 64, tid);
                CP_COMMIT();
            }
            uint32_t abase = sbase + (kc & 1) * 32768;
            uint32_t bbase = abase + 16384;

            #pragma unroll
            for (int kk = 0; kk < 4; kk++) {
                uint32_t af[4][4], bf[4][4];
                #pragma unroll
                for (int mt = 0; mt < 4; mt++) {
                    int ch = kk * 2 + a_ch;
                    ldsm_x4(af[mt][0], af[mt][1], af[mt][2], af[mt][3],
                            abase + a_rel[mt] + ((ch ^ a_rx[mt]) << 4));
                }
                #pragma unroll
                for (int nt4 = 0; nt4 < 4; nt4++) {
                    int ch = kk * 2 + b_ch;
                    ldsm_x4(bf[nt4][0], bf[nt4][1], bf[nt4][2], bf[nt4][3],
                            bbase + b_rel[nt4] + ((ch ^ b_rx[nt4]) << 4));
                }
                #pragma unroll
                for (int mt = 0; mt < 4; mt++)
                    #pragma unroll
                    for (int nt4 = 0; nt4 < 4; nt4++) {
                        mma16816(acc[mt][nt4 * 2],     af[mt], &bf[nt4][0]);
                        mma16816(acc[mt][nt4 * 2 + 1], af[mt], &bf[nt4][2]);
                    }
            }
        }

        // dump packed keys to Sc (clobbers buf1 region; mainloop done)
        __syncthreads();
        #pragma unroll
        for (int mt = 0; mt < 4; mt++) {
            int r = warp_m * 64 + mt * 16 + (lane >> 2);
            #pragma unroll
            for (int n8 = 0; n8 < 8; n8++) {
                int c = warp_n * 64 + n8 * 8 + 2 * (lane & 3);
                int cl = kt * 128 + c;
                uint2 k0 = make_uint2(packkey(acc[mt][n8][0], cl),
                                      packkey(acc[mt][n8][1], cl + 1));
                uint2 k1 = make_uint2(packkey(acc[mt][n8][2], cl),
                                      packkey(acc[mt][n8][3], cl + 1));
                *reinterpret_cast<uint2*>(&Sc[r][c])     = k0;
                *reinterpret_cast<uint2*>(&Sc[r + 8][c]) = k1;
            }
        }
        __syncthreads();

        // stage next kt's slice0 into buf0 (disjoint from Sc) — overlaps scan
        if (kt + 1 < CHUNK / 128) {
            stage64_async(sbase,         qbase, tid);
            stage64_async(sbase + 16384, kb + (size_t)(kb0 + 128) * DMODEL, tid);
            CP_COMMIT();
        }

        // scan: warp wid owns rows [wid*32, wid*32+32); half-warp reg lists
        #pragma unroll
        for (int s = 0; s < 16; s++) {
            int row = wid * 32 + 2 * s + half;
            const uint32_t* srcp = &Sc[row][hl * 8];
            uint4 v0 = *reinterpret_cast<const uint4*>(srcp);
            uint4 v1 = *reinterpret_cast<const uint4*>(srcp + 4);
            uint32_t thr = __shfl_sync(0xffffffffu, lst[s], (lane & 16) | 15);
            bool c = (v0.x > thr) | (v0.y > thr) | (v0.z > thr) | (v0.w > thr)
                   | (v1.x > thr) | (v1.y > thr) | (v1.z > thr) | (v1.w > thr);
            unsigned m = __ballot_sync(0xffffffffu, c);
            unsigned mlo = m & 0xffffu, mhi = m >> 16;
            while (mlo | mhi) {
                bool alo = mlo != 0, ahi = mhi != 0;
                int slo = alo ? (__ffs(mlo) - 1) : 0;
                int shi = ahi ? (__ffs(mhi) - 1) : 0;
                if (alo) mlo &= mlo - 1;
                if (ahi) mhi &= mhi - 1;
                int srcl = (half ? shi : slo) | (half << 4);
                bool act = half ? ahi : alo;
                uint32_t c0k = __shfl_sync(0xffffffffu, v0.x, srcl);
                uint32_t c1k = __shfl_sync(0xffffffffu, v0.y, srcl);
                uint32_t c2k = __shfl_sync(0xffffffffu, v0.z, srcl);
                uint32_t c3k = __shfl_sync(0xffffffffu, v0.w, srcl);
                uint32_t c4k = __shfl_sync(0xffffffffu, v1.x, srcl);
                uint32_t c5k = __shfl_sync(0xffffffffu, v1.y, srcl);
                uint32_t c6k = __shfl_sync(0xffffffffu, v1.z, srcl);
                uint32_t c7k = __shfl_sync(0xffffffffu, v1.w, srcl);
                ins16h(lst[s], c0k, act && (c0k > thr), lane);
                thr = __shfl_sync(0xffffffffu, lst[s], (lane & 16) | 15);
                ins16h(lst[s], c1k, act && (c1k > thr), lane);
                thr = __shfl_sync(0xffffffffu, lst[s], (lane & 16) | 15);
                ins16h(lst[s], c2k, act && (c2k > thr), lane);
                thr = __shfl_sync(0xffffffffu, lst[s], (lane & 16) | 15);
                ins16h(lst[s], c3k, act && (c3k > thr), lane);
                thr = __shfl_sync(0xffffffffu, lst[s], (lane & 16) | 15);
                ins16h(lst[s], c4k, act && (c4k > thr), lane);
                thr = __shfl_sync(0xffffffffu, lst[s], (lane & 16) | 15);
                ins16h(lst[s], c5k, act && (c5k > thr), lane);
                thr = __shfl_sync(0xffffffffu, lst[s], (lane & 16) | 15);
                ins16h(lst[s], c6k, act && (c6k > thr), lane);
                thr = __shfl_sync(0xffffffffu, lst[s], (lane & 16) | 15);
                ins16h(lst[s], c7k, act && (c7k > thr), lane);
                thr = __shfl_sync(0xffffffffu, lst[s], (lane & 16) | 15);
            }
        }
        __syncthreads();   // scan done before next mainloop clobbers Sc (buf1)
    }

    // write per-(row, chunk) 16-lists (entry = hl, row per half)
    #pragma unroll
    for (int s = 0; s < 16; s++) {
        int row = q0 + wid * 32 + 2 * s + half;
        part[((size_t)row * NCH + blockIdx.x) * KSEL + hl] = lst[s];
    }
}

// ---------------- merge 128 packed candidates/row -> top-32 -----------------
__global__ __launch_bounds__(256) void merge32_kernel(
    const uint32_t* __restrict__ part, int* __restrict__ cand)
{
    int lane = threadIdx.x & 31;
    int row  = blockIdx.x * 8 + (threadIdx.x >> 5);
    unsigned long long mk[4];
    #pragma unroll
    for (int j = 0; j < 4; j++) {
        int e = lane + 32 * j;                // 0..127 = chunk*16 + slot
        uint32_t key = part[(size_t)row * 128 + e];
        int gid = (e >> 4) * CHUNK + 4095 - (int)(key & 0xfffu);
        mk[j] = ((unsigned long long)(key >> 16) << 32) | (uint32_t)(0xffffffffu - gid);
    }
    for (int t = 0; t < NCAND; t++) {
        unsigned long long best = mk[0];
        #pragma unroll
        for (int j = 1; j < 4; j++) if (mk[j] > best) best = mk[j];
        #pragma unroll
        for (int o = 16; o > 0; o >>= 1) {
            unsigned long long ob = __shfl_xor_sync(0xffffffffu, best, o);
            if (ob > best) best = ob;
        }
        if (lane == 0)
            cand[row * NCAND + t] = (int)(0xffffffffu - (uint32_t)best);
        #pragma unroll
        for (int j = 0; j < 4; j++) if (mk[j] == best) mk[j] = 0;
    }
}

// ---------------- exact fp32 rescore of 32 candidates -> final top-16 -------
__global__ __launch_bounds__(256) void rescore_kernel(
    const float* __restrict__ q, const float* __restrict__ dbk,
    const int* __restrict__ cand, int* __restrict__ topk)
{
    __shared__ float sq[DMODEL];
    __shared__ float ss[NCAND];
    __shared__ int   sid[NCAND];
    int t = blockIdx.x, tid = threadIdx.x;
    int w = tid >> 5, lane = tid & 31;
    sq[tid]       = q[(size_t)t * DMODEL + tid];
    sq[tid + 256] = q[(size_t)t * DMODEL + tid + 256];
    sq[tid + 512] = q[(size_t)t * DMODEL + tid + 512];
    if (tid < NCAND) sid[tid] = cand[t * NCAND + tid];
    __syncthreads();

    for (int cc = w; cc < NCAND; cc += 8) {
        const float* kr = dbk + (size_t)sid[cc] * DMODEL;
        float p = 0.f;
        #pragma unroll
        for (int j = 0; j < DMODEL / 32; j++)
            p += sq[lane + 32 * j] * kr[lane + 32 * j];
        #pragma unroll
        for (int o = 16; o > 0; o >>= 1) p += __shfl_xor_sync(0xffffffffu, p, o);
        if (lane == 0) ss[cc] = p;
    }
    __syncthreads();

    if (w == 0) {
        float s = ss[lane];
        int  id = sid[lane];
        for (int it = 0; it < KSEL; it++) {
            float bs = s; int bid = id;
            #pragma unroll
            for (int o = 16; o > 0; o >>= 1) {
                float os = __shfl_xor_sync(0xffffffffu, bs, o);
                int   oi = __shfl_xor_sync(0xffffffffu, bid, o);
                if (better(os, oi, bs, bid)) { bs = os; bid = oi; }
            }
            if (lane == 0) topk[t * KSEL + it] = bid;
            if (id == bid) { s = -CUDART_INF_F; id = 0x7fffffff; }
        }
    }
}

// ---------------- per-token memory attention ---------------------------------
__global__ __launch_bounds__(384) void attn_kernel(
    const float* __restrict__ q, const float* __restrict__ dbk,
    const float* __restrict__ dbv, const int* __restrict__ topk,
    float* __restrict__ out)
{
    __shared__ float sq[DMODEL];
    __shared__ int   sidx[KSEL];
    __shared__ float saw[NH][KSEL];
    int t = blockIdx.x;
    int tid = threadIdx.x, lane = tid & 31, w = tid >> 5;
    sq[tid]       = q[(size_t)t * DMODEL + tid];
    sq[tid + 384] = q[(size_t)t * DMODEL + tid + 384];
    if (tid < KSEL) sidx[tid] = topk[t * KSEL + tid];
    __syncthreads();

    float q1 = sq[w * HD + lane], q2 = sq[w * HD + lane + 32];
    for (int m = 0; m < KSEL; m++) {
        const float* kr = dbk + (size_t)sidx[m] * DMODEL + w * HD;
        float p = q1 * kr[lane] + q2 * kr[lane + 32];
        #pragma unroll
        for (int o = 16; o > 0; o >>= 1) p += __shfl_xor_sync(0xffffffffu, p, o);
        if (lane == 0) saw[w][m] = p * 0.125f;
    }
    __syncwarp();
    {
        float x = (lane < KSEL) ? saw[w][lane] : -CUDART_INF_F;
        float mx = x;
        #pragma unroll
        for (int o = 16; o > 0; o >>= 1) mx = fmaxf(mx, __shfl_xor_sync(0xffffffffu, mx, o));
        float e = (lane < KSEL) ? expf(x - mx) : 0.f;
        float se = e;
        #pragma unroll
        for (int o = 16; o > 0; o >>= 1) se += __shfl_xor_sync(0xffffffffu, se, o);
        if (lane < KSEL) saw[w][lane] = e / se;
    }
    __syncwarp();
    float a1 = 0.f, a2 = 0.f;
    for (int m = 0; m < KSEL; m++) {
        float aw = saw[w][m];
        const float* vr = dbv + (size_t)sidx[m] * DMODEL + w * HD;
        a1 += aw * vr[lane]; a2 += aw * vr[lane + 32];
    }
    out[(size_t)t * DMODEL + w * HD + lane]      = a1;
    out[(size_t)t * DMODEL + w * HD + lane + 32] = a2;
}

// ---------------- launch -----------------------------------------------------
extern "C" void kernel_launch(void* const* d_in, const int* in_sizes, int n_in,
                              void* d_out, int out_size)
{
    const float* prev   = (const float*)d_in[0];
    const float* dbk    = (const float*)d_in[1];
    const float* dbv    = (const float*)d_in[2];
    const float* ln1g   = (const float*)d_in[3];
    const float* ln1b   = (const float*)d_in[4];
    const float* cattnw = (const float*)d_in[5];
    const float* cattnb = (const float*)d_in[6];
    const float* cprojw = (const float*)d_in[7];
    const float* cprojb = (const float*)d_in[8];
    const float* ln2g   = (const float*)d_in[9];
    const float* ln2b   = (const float*)d_in[10];
    const float* fcw    = (const float*)d_in[11];
    const float* fcb    = (const float*)d_in[12];
    const float* projw  = (const float*)d_in[13];
    const float* projb  = (const float*)d_in[14];
    float* out = (float*)d_out;

    float *p_ln, *p_q, *p_attn, *p_h, *p_ff1;
    __nv_bfloat16 *p_qb, *p_kb;
    uint32_t *p_part;
    int *p_cand, *p_topk;
    cudaGetSymbolAddress((void**)&p_ln,    g_ln);
    cudaGetSymbolAddress((void**)&p_q,     g_q);
    cudaGetSymbolAddress((void**)&p_attn,  g_attn);
    cudaGetSymbolAddress((void**)&p_h,     g_h);
    cudaGetSymbolAddress((void**)&p_ff1,   g_ff1);
    cudaGetSymbolAddress((void**)&p_qb,    g_qb);
    cudaGetSymbolAddress((void**)&p_kb,    g_kb);
    cudaGetSymbolAddress((void**)&p_part,  g_part);
    cudaGetSymbolAddress((void**)&p_cand,  g_cand);
    cudaGetSymbolAddress((void**)&p_topk,  g_topk);

    // 1. LN1
    ln_kernel<<<NTOK, 256>>>(prev, ln1g, ln1b, p_ln);

    // 2. q = LN1(x) @ c_attn_w[:, :768] + bias  (fp32 — preserves selection)
    sgemm_kernel<EPI_BIAS><<<dim3(DMODEL / 128, NTOK / 128), 256>>>(
        p_ln, DMODEL, cattnw, 3 * DMODEL, cattnb, nullptr, p_q, DMODEL, DMODEL);

    // 3. bf16 conversions (single launch)
    {
        int nq4 = NTOK * DMODEL / 4;
        int nk4 = MDB * DMODEL / 4;
        f2bf2_kernel<<<(nq4 + nk4) / 256, 256>>>(p_q, p_qb, dbk, p_kb, nq4);
    }

    // 4. bf16 mma.sync score GEMM + register top-16 (4 warps, 64x64 tiles)
    int smem = 32768 + 128 * 132 * 4;  // 100352 B
    cudaFuncSetAttribute(score_topk_mma,
                         cudaFuncAttributeMaxDynamicSharedMemorySize, smem);
    score_topk_mma<<<dim3(NCH, NTOK / 128), 128, smem>>>(p_qb, p_kb, p_part);

    // 5. merge 128 packed candidates -> top-32 per token
    merge32_kernel<<<NTOK / 8, 256>>>(p_part, p_cand);

    // 6. exact fp32 rescore of top-32 -> final top-16 (jax tie-break)
    rescore_kernel<<<NTOK, 256>>>(p_q, dbk, p_cand, p_topk);

    // 7. per-token per-head softmax attention over 16 gathered memories
    attn_kernel<<<NTOK, 384>>>(p_q, dbk, dbv, p_topk, p_attn);

    // 8. h = attn @ c_proj_w + bias + residual   (tf32 tensor cores)
    tgemm_kernel<EPI_BIAS_RES><<<dim3(DMODEL / 128, NTOK / 128), 256>>>(
        p_attn, DMODEL, cprojw, DMODEL, cprojb, prev, p_h, DMODEL, DMODEL);

    // 9. LN2
    ln_kernel<<<NTOK, 256>>>(p_h, ln2g, ln2b, p_ln);

    // 10. ff1 = gelu(LN2(h) @ fc_w + fc_b)       (tf32)
    tgemm_kernel<EPI_GELU><<<dim3(DFF / 128, NTOK / 128), 256>>>(
        p_ln, DMODEL, fcw, DFF, fcb, nullptr, p_ff1, DFF, DMODEL);

    // 11. out = ff1 @ proj_w + proj_b + h        (tf32)
    tgemm_kernel<EPI_BIAS_RES><<<dim3(DMODEL / 128, NTOK / 128), 256>>>(
        p_ff1, DFF, projw, DMODEL, projb, p_h, out, DMODEL, DFF);
}

// round 8
// speedup vs baseline: 1.2807x; 1.2807x over previous
#include <cuda_runtime.h>
#include <cuda_bf16.h>
#include <math_constants.h>
#include <cstdint>

#define NTOK   4096
#define DMODEL 768
#define NH     12
#define HD     64
#define KSEL   16
#define MDB    32768
#define NCH    8
#define CHUNK  (MDB/NCH)   /* 4096 keys per chunk */
#define DFF    3072
#define NCAND  32          /* rescored candidates per token */

#define W_CPROJ_OFF 0
#define W_FC_OFF    (DMODEL*DMODEL)
#define W_PROJ_OFF  (DMODEL*DMODEL + DMODEL*DFF)
#define W_TOTAL     (DMODEL*DMODEL + 2*DMODEL*DFF)   /* 5308416 floats */

// ---------------- scratch (device globals; no allocation allowed) ----------
__device__ float g_ln  [NTOK*DMODEL];
__device__ float g_q   [NTOK*DMODEL];
__device__ float g_attn[NTOK*DMODEL];
__device__ float g_h   [NTOK*DMODEL];
__device__ float g_ff1 [NTOK*DFF];
__device__ float g_wr  [W_TOTAL];            // tf32-rounded weights
__device__ __nv_bfloat16 g_qb[NTOK*DMODEL];
__device__ __nv_bfloat16 g_kb[MDB*DMODEL];
__device__ uint32_t g_part[NTOK*NCH*KSEL];   // packed (ord16<<16 | 4095-lidx)
__device__ int   g_cand  [NTOK*NCAND];
__device__ int   g_topk  [NTOK*KSEL];

// ---------------- helpers ---------------------------------------------------
__device__ __forceinline__ uint32_t smem_u32(const void* p) {
    uint32_t a;
    asm("{ .reg .u64 t; cvta.to.shared.u64 t, %1; cvt.u32.u64 %0, t; }" : "=r"(a) : "l"(p));
    return a;
}

__device__ __forceinline__ void ldsm_x4(uint32_t& r0, uint32_t& r1,
                                        uint32_t& r2, uint32_t& r3, uint32_t addr) {
    asm volatile("ldmatrix.sync.aligned.m8n8.x4.shared.b16 {%0,%1,%2,%3}, [%4];"
                 : "=r"(r0), "=r"(r1), "=r"(r2), "=r"(r3) : "r"(addr));
}

__device__ __forceinline__ void mma16816(float* c, const uint32_t* a, const uint32_t* b) {
    asm("mma.sync.aligned.m16n8k16.row.col.f32.bf16.bf16.f32 "
        "{%0,%1,%2,%3}, {%4,%5,%6,%7}, {%8,%9}, {%0,%1,%2,%3};"
        : "+f"(c[0]), "+f"(c[1]), "+f"(c[2]), "+f"(c[3])
        : "r"(a[0]), "r"(a[1]), "r"(a[2]), "r"(a[3]), "r"(b[0]), "r"(b[1]));
}

__device__ __forceinline__ uint32_t f2tf32(float f) {
    uint32_t o; asm("cvt.rna.tf32.f32 %0, %1;" : "=r"(o) : "f"(f)); return o;
}
__device__ __forceinline__ float tf32r(float f) {
    return __uint_as_float(f2tf32(f));
}

__device__ __forceinline__ void mma_tf32(float* c, const uint32_t* a, const uint32_t* b) {
    asm("mma.sync.aligned.m16n8k8.row.col.f32.tf32.tf32.f32 "
        "{%0,%1,%2,%3}, {%4,%5,%6,%7}, {%8,%9}, {%0,%1,%2,%3};"
        : "+f"(c[0]), "+f"(c[1]), "+f"(c[2]), "+f"(c[3])
        : "r"(a[0]), "r"(a[1]), "r"(a[2]), "r"(a[3]), "r"(b[0]), "r"(b[1]));
}

#define CP_ASYNC16(dst, src) \
    asm volatile("cp.async.cg.shared.global [%0], [%1], 16;" :: "r"(dst), "l"(src))
#define CP_COMMIT()  asm volatile("cp.async.commit_group;" ::: "memory")
#define CP_WAIT0()   asm volatile("cp.async.wait_group 0;" ::: "memory")

__device__ __forceinline__ float blockReduceSum(float v, float* red) {
    #pragma unroll
    for (int o = 16; o > 0; o >>= 1) v += __shfl_xor_sync(0xffffffffu, v, o);
    int w = threadIdx.x >> 5, l = threadIdx.x & 31;
    if (l == 0) red[w] = v;
    __syncthreads();
    if (w == 0) {
        float t = (l < 8) ? red[l] : 0.f;
        #pragma unroll
        for (int o = 4; o > 0; o >>= 1) t += __shfl_xor_sync(0xffffffffu, t, o);
        if (l == 0) red[0] = t;
    }
    __syncthreads();
    float r = red[0];
    __syncthreads();
    return r;
}

__device__ __forceinline__ float gelu_tanh(float x) {
    return 0.5f * x * (1.f + tanhf(0.7978845608028654f * (x + 0.044715f * x * x * x)));
}

__device__ __forceinline__ bool better(float s1, int i1, float s2, int i2) {
    return (s1 > s2) || (s1 == s2 && i1 < i2);
}

// pack score (bf16-order-preserving) + local idx into one sortable uint32
__device__ __forceinline__ uint32_t packkey(float s, int colLocal) {
    uint16_t b = __bfloat16_as_ushort(__float2bfloat16(s));
    uint16_t o = (b & 0x8000) ? (uint16_t)(~b) : (uint16_t)(b | 0x8000);
    return ((uint32_t)o << 16) | (uint32_t)(4095 - colLocal);
}

// warp-wide insert of key k into sorted-desc list (entry `lane`, lanes 0..15)
__device__ __forceinline__ void ins16(uint32_t& val, uint32_t k, int lane) {
    unsigned gt = __ballot_sync(0xffffffffu, k > val);
    uint32_t up = __shfl_up_sync(0xffffffffu, val, 1);
    if (gt) {
        int p = __ffs(gt) - 1;
        if (lane > p && lane < 16) val = up;
        if (lane == p) val = k;
    }
}

// ---------------- layernorm (ROUND: tf32-round the output) ------------------
template <bool ROUND>
__global__ __launch_bounds__(256) void ln_kernel(
    const float* __restrict__ x, const float* __restrict__ g,
    const float* __restrict__ b, float* __restrict__ y)
{
    __shared__ float red[8];
    int row = blockIdx.x;
    const float* xr = x + (size_t)row * DMODEL;
    int t = threadIdx.x;
    float v0 = xr[t], v1 = xr[t + 256], v2 = xr[t + 512];
    float mu = blockReduceSum(v0 + v1 + v2, red) * (1.f / DMODEL);
    float d0 = v0 - mu, d1 = v1 - mu, d2 = v2 - mu;
    float var = blockReduceSum(d0 * d0 + d1 * d1 + d2 * d2, red) * (1.f / DMODEL);
    float rs = rsqrtf(var + 1e-5f);
    float* yr = y + (size_t)row * DMODEL;
    float o0 = d0 * rs * g[t]       + b[t];
    float o1 = d1 * rs * g[t + 256] + b[t + 256];
    float o2 = d2 * rs * g[t + 512] + b[t + 512];
    if (ROUND) { o0 = tf32r(o0); o1 = tf32r(o1); o2 = tf32r(o2); }
    yr[t] = o0; yr[t + 256] = o1; yr[t + 512] = o2;
}

// ---------------- combined fp32 -> bf16 convert (q then dbk) ----------------
__global__ __launch_bounds__(256) void f2bf2_kernel(
    const float* __restrict__ xq, __nv_bfloat16* __restrict__ yq,
    const float* __restrict__ xk, __nv_bfloat16* __restrict__ yk, int nq4)
{
    int i = blockIdx.x * 256 + threadIdx.x;
    const float* src; __nv_bfloat16* dst; int j;
    if (i < nq4) { src = xq; dst = yq; j = i; }
    else         { src = xk; dst = yk; j = i - nq4; }
    float4 v = reinterpret_cast<const float4*>(src)[j];
    __nv_bfloat162 a = __floats2bfloat162_rn(v.x, v.y);
    __nv_bfloat162 b = __floats2bfloat162_rn(v.z, v.w);
    reinterpret_cast<__nv_bfloat162*>(dst)[2 * j]     = a;
    reinterpret_cast<__nv_bfloat162*>(dst)[2 * j + 1] = b;
}

// ---------------- tf32-round the 3 value-path weight matrices ----------------
__global__ __launch_bounds__(256) void roundw_kernel(
    const float* __restrict__ w1, const float* __restrict__ w2,
    const float* __restrict__ w3, float* __restrict__ dst)
{
    int i = blockIdx.x * 256 + threadIdx.x;       // float4 index
    const int n1 = (DMODEL * DMODEL) / 4;
    const int n2 = (DMODEL * DFF) / 4;
    const float* src; int j;
    if (i < n1)           { src = w1; j = i; }
    else if (i < n1 + n2) { src = w2; j = i - n1; }
    else                  { src = w3; j = i - n1 - n2; }
    float4 v = reinterpret_cast<const float4*>(src)[j];
    v.x = tf32r(v.x); v.y = tf32r(v.y); v.z = tf32r(v.z); v.w = tf32r(v.w);
    reinterpret_cast<float4*>(dst)[i] = v;
}

// ---------------- fp32 SGEMM (only used for q; preserves selection) ---------
enum { EPI_BIAS = 0, EPI_BIAS_RES = 1, EPI_GELU = 2 };

template <int EPI>
__global__ __launch_bounds__(256) void sgemm_kernel(
    const float* __restrict__ A, int lda,
    const float* __restrict__ B, int ldb,
    const float* __restrict__ bias,
    const float* __restrict__ res,
    float* __restrict__ C, int ldc, int Kd)
{
    __shared__ float As[8][128];
    __shared__ float Bs[8][128];
    int tid  = threadIdx.x;
    int brow = blockIdx.y * 128, bcol = blockIdx.x * 128;
    int arow = tid >> 1, acol = (tid & 1) * 4;
    int bkr  = tid >> 5, bcol4 = (tid & 31) * 4;
    const float* Ap = A + (size_t)(brow + arow) * lda + acol;
    const float* Bp = B + (size_t)bkr * ldb + bcol + bcol4;
    int rbase = (tid >> 4) * 4, cbase = (tid & 15) * 4;

    float acc[8][8];
    #pragma unroll
    for (int i = 0; i < 8; i++)
        #pragma unroll
        for (int j = 0; j < 8; j++) acc[i][j] = 0.f;

    for (int k0 = 0; k0 < Kd; k0 += 8) {
        float4 av = *reinterpret_cast<const float4*>(Ap + k0);
        float4 bv = *reinterpret_cast<const float4*>(Bp + (size_t)k0 * ldb);
        __syncthreads();
        As[acol + 0][arow] = av.x; As[acol + 1][arow] = av.y;
        As[acol + 2][arow] = av.z; As[acol + 3][arow] = av.w;
        *reinterpret_cast<float4*>(&Bs[bkr][bcol4]) = bv;
        __syncthreads();
        #pragma unroll
        for (int kk = 0; kk < 8; kk++) {
            float a[8], bb[8];
            *reinterpret_cast<float4*>(a)      = *reinterpret_cast<const float4*>(&As[kk][rbase]);
            *reinterpret_cast<float4*>(a + 4)  = *reinterpret_cast<const float4*>(&As[kk][rbase + 64]);
            *reinterpret_cast<float4*>(bb)     = *reinterpret_cast<const float4*>(&Bs[kk][cbase]);
            *reinterpret_cast<float4*>(bb + 4) = *reinterpret_cast<const float4*>(&Bs[kk][cbase + 64]);
            #pragma unroll
            for (int i = 0; i < 8; i++)
                #pragma unroll
                for (int j = 0; j < 8; j++) acc[i][j] += a[i] * bb[j];
        }
    }

    #pragma unroll
    for (int i = 0; i < 8; i++) {
        int r = brow + rbase + ((i < 4) ? i : 60 + i);
        #pragma unroll
        for (int jg = 0; jg < 2; jg++) {
            int c = bcol + cbase + jg * 64;
            float4 bi = *reinterpret_cast<const float4*>(bias + c);
            float4 v;
            v.x = acc[i][jg * 4 + 0] + bi.x;
            v.y = acc[i][jg * 4 + 1] + bi.y;
            v.z = acc[i][jg * 4 + 2] + bi.z;
            v.w = acc[i][jg * 4 + 3] + bi.w;
            if (EPI == EPI_BIAS_RES) {
                float4 rv = *reinterpret_cast<const float4*>(res + (size_t)r * ldc + c);
                v.x += rv.x; v.y += rv.y; v.z += rv.z; v.w += rv.w;
            } else if (EPI == EPI_GELU) {
                v.x = gelu_tanh(v.x); v.y = gelu_tanh(v.y);
                v.z = gelu_tanh(v.z); v.w = gelu_tanh(v.w);
            }
            *reinterpret_cast<float4*>(C + (size_t)r * ldc + c) = v;
        }
    }
}

// ---------------- tf32 tensor-core GEMM, cp.async double-buffered -----------
// Inputs (A and B) are PRE-ROUNDED to tf32 by their producers; no inner cvt.
// GELU_ROUND_OUT: EPI_GELU epilogue tf32-rounds its output (feeds proj GEMM).
#define A_STR 20
#define B_STR 136
#define A_BUF (128 * A_STR)
#define B_BUF (16 * B_STR)

template <int EPI>
__global__ __launch_bounds__(256, 2) void tgemm_kernel(
    const float* __restrict__ A, int lda,
    const float* __restrict__ B, int ldb,
    const float* __restrict__ bias,
    const float* __restrict__ res,
    float* __restrict__ C, int ldc, int Kd)
{
    __shared__ float As[2 * A_BUF];
    __shared__ float Bs[2 * B_BUF];
    uint32_t sA = smem_u32(As), sB = smem_u32(Bs);
    int tid = threadIdx.x, lane = tid & 31, wid = tid >> 5;
    int warp_m = wid >> 2, warp_n = wid & 3;
    int brow = blockIdx.y * 128, bcol = blockIdx.x * 128;

    float acc[4][4][4];
    #pragma unroll
    for (int mt = 0; mt < 4; mt++)
        #pragma unroll
        for (int nt = 0; nt < 4; nt++)
            #pragma unroll
            for (int r = 0; r < 4; r++) acc[mt][nt][r] = 0.f;

    auto stageA = [&](int kb, int buf) {
        #pragma unroll
        for (int it = 0; it < 2; it++) {
            int c = tid + it * 256;        // 512 chunks of 16B: row, k-quarter
            int row = c >> 2, k4 = c & 3;
            uint32_t d = sA + (buf * A_BUF + row * A_STR + k4 * 4) * 4;
            const void* s = A + (size_t)(brow + row) * lda + kb + k4 * 4;
            CP_ASYNC16(d, s);
        }
    };
    auto stageB = [&](int kb, int buf) {
        #pragma unroll
        for (int it = 0; it < 2; it++) {
            int c = tid + it * 256;
            int k = c >> 5, n4 = c & 31;
            uint32_t d = sB + (buf * B_BUF + k * B_STR + n4 * 4) * 4;
            const void* s = B + (size_t)(kb + k) * ldb + bcol + n4 * 4;
            CP_ASYNC16(d, s);
        }
    };

    stageA(0, 0); stageB(0, 0); CP_COMMIT();

    int niter = Kd / 16;
    for (int i = 0; i < niter; i++) {
        CP_WAIT0();
        __syncthreads();
        if (i + 1 < niter) {
            stageA((i + 1) * 16, (i + 1) & 1);
            stageB((i + 1) * 16, (i + 1) & 1);
            CP_COMMIT();
        }
        const float* Af = As + (i & 1) * A_BUF;
        const float* Bf = Bs + (i & 1) * B_BUF;

        #pragma unroll
        for (int j = 0; j < 2; j++) {
            uint32_t a[4][4], b[4][2];
            #pragma unroll
            for (int mt = 0; mt < 4; mt++) {
                int r = warp_m * 64 + mt * 16 + (lane >> 2);
                const float* pa = Af + r * A_STR + j * 8 + (lane & 3);
                a[mt][0] = __float_as_uint(pa[0]);
                a[mt][1] = __float_as_uint(pa[8 * A_STR]);
                a[mt][2] = __float_as_uint(pa[4]);
                a[mt][3] = __float_as_uint(pa[8 * A_STR + 4]);
            }
            #pragma unroll
            for (int nt = 0; nt < 4; nt++) {
                int n = warp_n * 32 + nt * 8 + (lane >> 2);
                const float* pb = Bf + (j * 8 + (lane & 3)) * B_STR + n;
                b[nt][0] = __float_as_uint(pb[0]);
                b[nt][1] = __float_as_uint(pb[4 * B_STR]);
            }
            #pragma unroll
            for (int mt = 0; mt < 4; mt++)
                #pragma unroll
                for (int nt = 0; nt < 4; nt++)
                    mma_tf32(acc[mt][nt], a[mt], b[nt]);
        }
    }

    #pragma unroll
    for (int mt = 0; mt < 4; mt++) {
        #pragma unroll
        for (int rh = 0; rh < 2; rh++) {
            int r = brow + warp_m * 64 + mt * 16 + rh * 8 + (lane >> 2);
            #pragma unroll
            for (int nt = 0; nt < 4; nt++) {
                int c = bcol + warp_n * 32 + nt * 8 + 2 * (lane & 3);
                float2 v;
                v.x = acc[mt][nt][rh * 2 + 0] + bias[c];
                v.y = acc[mt][nt][rh * 2 + 1] + bias[c + 1];
                if (EPI == EPI_BIAS_RES) {
                    float2 rv = *reinterpret_cast<const float2*>(res + (size_t)r * ldc + c);
                    v.x += rv.x; v.y += rv.y;
                } else if (EPI == EPI_GELU) {
                    v.x = tf32r(gelu_tanh(v.x));   // feeds proj GEMM as A
                    v.y = tf32r(gelu_tanh(v.y));
                }
                *reinterpret_cast<float2*>(C + (size_t)r * ldc + c) = v;
            }
        }
    }
}

// ---------------- bf16 mma.sync score GEMM + register top-16 (R6 proven) ----
// grid(NCH, 32); CTA = 128 q x 4096-key chunk, K=768 in 12 slices of 64.
// smem 100352 B: buf0 A@0 B@16K; buf1 A@32K B@48K; Sc uint32[128][132] @32K
// (Sc overlaps buf1 only; buf0 disjoint -> next-kt slice0 stages during scan).
#define SC_SC 32768

__device__ __forceinline__ void stage64_async(
    uint32_t dstb, const __nv_bfloat16* __restrict__ src, int tid)
{
    #pragma unroll
    for (int it = 0; it < 4; it++) {
        int c = tid + it * 256;          // 1024 chunks = 128 rows x 8 x 16B
        int row = c >> 3, col = c & 7;
        uint32_t d = dstb + row * 128 + ((col ^ (row & 7)) << 4);
        const void* s = src + (size_t)row * DMODEL + col * 8;
        CP_ASYNC16(d, s);
    }
}

__global__ __launch_bounds__(256, 2) void score_topk_mma(
    const __nv_bfloat16* __restrict__ qb, const __nv_bfloat16* __restrict__ kb,
    uint32_t* __restrict__ part)
{
    extern __shared__ char dsm[];
    uint32_t (*Sc)[132] = (uint32_t(*)[132])(dsm + SC_SC);
    uint32_t sbase = smem_u32(dsm);

    int tid = threadIdx.x, lane = tid & 31, wid = tid >> 5;
    int warp_m = wid >> 2, warp_n = wid & 3;
    int q0 = blockIdx.y * 128;
    int c0 = blockIdx.x * CHUNK;

    // register top-16 lists: lst[r] = entry `lane` of row (wid*16+r), sorted desc
    uint32_t lst[16];
    #pragma unroll
    for (int r = 0; r < 16; r++) lst[r] = (lane < 16) ? 0u : 0xffffffffu;

    uint32_t a_rel[4], b_rel[2];
    int a_rx[4], b_rx[2];
    #pragma unroll
    for (int mt = 0; mt < 4; mt++) {
        int row = warp_m * 64 + mt * 16 + (lane & 15);
        a_rel[mt] = row * 128;
        a_rx[mt] = row & 7;
    }
    #pragma unroll
    for (int pr = 0; pr < 2; pr++) {
        int row = warp_n * 32 + pr * 16 + (lane & 7) + ((lane >> 4) << 3);
        b_rel[pr] = row * 128;
        b_rx[pr] = row & 7;
    }
    int a_ch = lane >> 4;
    int b_ch = (lane >> 3) & 1;

    const __nv_bfloat16* qbase = qb + (size_t)q0 * DMODEL;

    // prologue: stage kt=0 slice 0 into buf0
    stage64_async(sbase,         qbase, tid);
    stage64_async(sbase + 16384, kb + (size_t)c0 * DMODEL, tid);
    CP_COMMIT();

    for (int kt = 0; kt < CHUNK / 128; kt++) {
        int kb0 = c0 + kt * 128;
        const __nv_bfloat16* kbase = kb + (size_t)kb0 * DMODEL;

        float acc[4][4][4];
        #pragma unroll
        for (int mt = 0; mt < 4; mt++)
            #pragma unroll
            for (int nt = 0; nt < 4; nt++)
                #pragma unroll
                for (int r = 0; r < 4; r++) acc[mt][nt][r] = 0.f;

        for (int kc = 0; kc < DMODEL / 64; kc++) {
            CP_WAIT0();
            __syncthreads();
            if (kc + 1 < DMODEL / 64) {   // prefetch next slice of this kt
                uint32_t nb = sbase + ((kc + 1) & 1) * 32768;
                stage64_async(nb,         qbase + (kc + 1) * 64, tid);
                stage64_async(nb + 16384, kbase + (kc + 1) * 64, tid);
                CP_COMMIT();
            }
            uint32_t abase = sbase + (kc & 1) * 32768;
            uint32_t bbase = abase + 16384;

            #pragma unroll
            for (int kk = 0; kk < 4; kk++) {
                uint32_t af[4][4], bf[2][4];
                #pragma unroll
                for (int mt = 0; mt < 4; mt++) {
                    int ch = kk * 2 + a_ch;
                    ldsm_x4(af[mt][0], af[mt][1], af[mt][2], af[mt][3],
                            abase + a_rel[mt] + ((ch ^ a_rx[mt]) << 4));
                }
                #pragma unroll
                for (int pr = 0; pr < 2; pr++) {
                    int ch = kk * 2 + b_ch;
                    ldsm_x4(bf[pr][0], bf[pr][1], bf[pr][2], bf[pr][3],
                            bbase + b_rel[pr] + ((ch ^ b_rx[pr]) << 4));
                }
                #pragma unroll
                for (int mt = 0; mt < 4; mt++) {
                    mma16816(acc[mt][0], af[mt], &bf[0][0]);
                    mma16816(acc[mt][1], af[mt], &bf[0][2]);
                    mma16816(acc[mt][2], af[mt], &bf[1][0]);
                    mma16816(acc[mt][3], af[mt], &bf[1][2]);
                }
            }
        }

        // dump packed keys to Sc (clobbers buf1 region; mainloop done)
        __syncthreads();
        #pragma unroll
        for (int mt = 0; mt < 4; mt++) {
            int r = warp_m * 64 + mt * 16 + (lane >> 2);
            #pragma unroll
            for (int nt = 0; nt < 4; nt++) {
                int c = warp_n * 32 + nt * 8 + 2 * (lane & 3);
                int cl = kt * 128 + c;
                uint2 k0 = make_uint2(packkey(acc[mt][nt][0], cl),
                                      packkey(acc[mt][nt][1], cl + 1));
                uint2 k1 = make_uint2(packkey(acc[mt][nt][2], cl),
                                      packkey(acc[mt][nt][3], cl + 1));
                *reinterpret_cast<uint2*>(&Sc[r][c])     = k0;
                *reinterpret_cast<uint2*>(&Sc[r + 8][c]) = k1;
            }
        }
        __syncthreads();

        // stage next kt's slice0 into buf0 (disjoint from Sc) — overlaps scan
        if (kt + 1 < CHUNK / 128) {
            stage64_async(sbase,         qbase, tid);
            stage64_async(sbase + 16384, kb + (size_t)(kb0 + 128) * DMODEL, tid);
            CP_COMMIT();
        }

        // scan: warp wid owns rows [wid*16, wid*16+16); register lists
        #pragma unroll
        for (int r = 0; r < 16; r++) {
            int row = wid * 16 + r;
            uint4 kv = *reinterpret_cast<const uint4*>(&Sc[row][lane * 4]);
            uint32_t thr = __shfl_sync(0xffffffffu, lst[r], 15);
            bool c = (kv.x > thr) | (kv.y > thr) | (kv.z > thr) | (kv.w > thr);
            unsigned m = __ballot_sync(0xffffffffu, c);
            while (m) {
                int src = __ffs(m) - 1; m &= m - 1;
                uint32_t k0 = __shfl_sync(0xffffffffu, kv.x, src);
                uint32_t k1 = __shfl_sync(0xffffffffu, kv.y, src);
                uint32_t k2 = __shfl_sync(0xffffffffu, kv.z, src);
                uint32_t k3 = __shfl_sync(0xffffffffu, kv.w, src);
                thr = __shfl_sync(0xffffffffu, lst[r], 15);
                if (k0 > thr) { ins16(lst[r], k0, lane); thr = __shfl_sync(0xffffffffu, lst[r], 15); }
                if (k1 > thr) { ins16(lst[r], k1, lane); thr = __shfl_sync(0xffffffffu, lst[r], 15); }
                if (k2 > thr) { ins16(lst[r], k2, lane); thr = __shfl_sync(0xffffffffu, lst[r], 15); }
                if (k3 > thr) { ins16(lst[r], k3, lane); }
            }
        }
        __syncthreads();   // scan done before next mainloop clobbers Sc (buf1)
    }

    // write per-(row, chunk) 16-lists
    if (lane < 16) {
        #pragma unroll
        for (int r = 0; r < 16; r++) {
            int row = q0 + wid * 16 + r;
            part[((size_t)row * NCH + blockIdx.x) * KSEL + lane] = lst[r];
        }
    }
}

// ---------------- merge 128 packed candidates/row -> top-32 -----------------
__global__ __launch_bounds__(256) void merge32_kernel(
    const uint32_t* __restrict__ part, int* __restrict__ cand)
{
    int lane = threadIdx.x & 31;
    int row  = blockIdx.x * 8 + (threadIdx.x >> 5);
    unsigned long long mk[4];
    #pragma unroll
    for (int j = 0; j < 4; j++) {
        int e = lane + 32 * j;                // 0..127 = chunk*16 + slot
        uint32_t key = part[(size_t)row * 128 + e];
        int gid = (e >> 4) * CHUNK + 4095 - (int)(key & 0xfffu);
        mk[j] = ((unsigned long long)(key >> 16) << 32) | (uint32_t)(0xffffffffu - gid);
    }
    for (int t = 0; t < NCAND; t++) {
        unsigned long long best = mk[0];
        #pragma unroll
        for (int j = 1; j < 4; j++) if (mk[j] > best) best = mk[j];
        #pragma unroll
        for (int o = 16; o > 0; o >>= 1) {
            unsigned long long ob = __shfl_xor_sync(0xffffffffu, best, o);
            if (ob > best) best = ob;
        }
        if (lane == 0)
            cand[row * NCAND + t] = (int)(0xffffffffu - (uint32_t)best);
        #pragma unroll
        for (int j = 0; j < 4; j++) if (mk[j] == best) mk[j] = 0;
    }
}

// ---------------- exact fp32 rescore of 32 candidates -> final top-16 -------
__global__ __launch_bounds__(256) void rescore_kernel(
    const float* __restrict__ q, const float* __restrict__ dbk,
    const int* __restrict__ cand, int* __restrict__ topk)
{
    __shared__ float sq[DMODEL];
    __shared__ float ss[NCAND];
    __shared__ int   sid[NCAND];
    int t = blockIdx.x, tid = threadIdx.x;
    int w = tid >> 5, lane = tid & 31;
    sq[tid]       = q[(size_t)t * DMODEL + tid];
    sq[tid + 256] = q[(size_t)t * DMODEL + tid + 256];
    sq[tid + 512] = q[(size_t)t * DMODEL + tid + 512];
    if (tid < NCAND) sid[tid] = cand[t * NCAND + tid];
    __syncthreads();

    for (int cc = w; cc < NCAND; cc += 8) {
        const float* kr = dbk + (size_t)sid[cc] * DMODEL;
        float p = 0.f;
        #pragma unroll
        for (int j = 0; j < DMODEL / 32; j++)
            p += sq[lane + 32 * j] * kr[lane + 32 * j];
        #pragma unroll
        for (int o = 16; o > 0; o >>= 1) p += __shfl_xor_sync(0xffffffffu, p, o);
        if (lane == 0) ss[cc] = p;
    }
    __syncthreads();

    if (w == 0) {
        float s = ss[lane];
        int  id = sid[lane];
        for (int it = 0; it < KSEL; it++) {
            float bs = s; int bid = id;
            #pragma unroll
            for (int o = 16; o > 0; o >>= 1) {
                float os = __shfl_xor_sync(0xffffffffu, bs, o);
                int   oi = __shfl_xor_sync(0xffffffffu, bid, o);
                if (better(os, oi, bs, bid)) { bs = os; bid = oi; }
            }
            if (lane == 0) topk[t * KSEL + it] = bid;
            if (id == bid) { s = -CUDART_INF_F; id = 0x7fffffff; }
        }
    }
}

// ---------------- per-token memory attention (tf32-rounded output) ----------
__global__ __launch_bounds__(384) void attn_kernel(
    const float* __restrict__ q, const float* __restrict__ dbk,
    const float* __restrict__ dbv, const int* __restrict__ topk,
    float* __restrict__ out)
{
    __shared__ float sq[DMODEL];
    __shared__ int   sidx[KSEL];
    __shared__ float saw[NH][KSEL];
    int t = blockIdx.x;
    int tid = threadIdx.x, lane = tid & 31, w = tid >> 5;
    sq[tid]       = q[(size_t)t * DMODEL + tid];
    sq[tid + 384] = q[(size_t)t * DMODEL + tid + 384];
    if (tid < KSEL) sidx[tid] = topk[t * KSEL + tid];
    __syncthreads();

    float q1 = sq[w * HD + lane], q2 = sq[w * HD + lane + 32];
    for (int m = 0; m < KSEL; m++) {
        const float* kr = dbk + (size_t)sidx[m] * DMODEL + w * HD;
        float p = q1 * kr[lane] + q2 * kr[lane + 32];
        #pragma unroll
        for (int o = 16; o > 0; o >>= 1) p += __shfl_xor_sync(0xffffffffu, p, o);
        if (lane == 0) saw[w][m] = p * 0.125f;
    }
    __syncwarp();
    {
        float x = (lane < KSEL) ? saw[w][lane] : -CUDART_INF_F;
        float mx = x;
        #pragma unroll
        for (int o = 16; o > 0; o >>= 1) mx = fmaxf(mx, __shfl_xor_sync(0xffffffffu, mx, o));
        float e = (lane < KSEL) ? expf(x - mx) : 0.f;
        float se = e;
        #pragma unroll
        for (int o = 16; o > 0; o >>= 1) se += __shfl_xor_sync(0xffffffffu, se, o);
        if (lane < KSEL) saw[w][lane] = e / se;
    }
    __syncwarp();
    float a1 = 0.f, a2 = 0.f;
    for (int m = 0; m < KSEL; m++) {
        float aw = saw[w][m];
        const float* vr = dbv + (size_t)sidx[m] * DMODEL + w * HD;
        a1 += aw * vr[lane]; a2 += aw * vr[lane + 32];
    }
    // tf32-round: this tensor is consumed only as A of the c_proj tf32 GEMM
    out[(size_t)t * DMODEL + w * HD + lane]      = tf32r(a1);
    out[(size_t)t * DMODEL + w * HD + lane + 32] = tf32r(a2);
}

// ---------------- launch -----------------------------------------------------
extern "C" void kernel_launch(void* const* d_in, const int* in_sizes, int n_in,
                              void* d_out, int out_size)
{
    const float* prev   = (const float*)d_in[0];
    const float* dbk    = (const float*)d_in[1];
    const float* dbv    = (const float*)d_in[2];
    const float* ln1g   = (const float*)d_in[3];
    const float* ln1b   = (const float*)d_in[4];
    const float* cattnw = (const float*)d_in[5];
    const float* cattnb = (const float*)d_in[6];
    const float* cprojw = (const float*)d_in[7];
    const float* cprojb = (const float*)d_in[8];
    const float* ln2g   = (const float*)d_in[9];
    const float* ln2b   = (const float*)d_in[10];
    const float* fcw    = (const float*)d_in[11];
    const float* fcb    = (const float*)d_in[12];
    const float* projw  = (const float*)d_in[13];
    const float* projb  = (const float*)d_in[14];
    float* out = (float*)d_out;

    float *p_ln, *p_q, *p_attn, *p_h, *p_ff1, *p_wr;
    __nv_bfloat16 *p_qb, *p_kb;
    uint32_t *p_part;
    int *p_cand, *p_topk;
    cudaGetSymbolAddress((void**)&p_ln,    g_ln);
    cudaGetSymbolAddress((void**)&p_q,     g_q);
    cudaGetSymbolAddress((void**)&p_attn,  g_attn);
    cudaGetSymbolAddress((void**)&p_h,     g_h);
    cudaGetSymbolAddress((void**)&p_ff1,   g_ff1);
    cudaGetSymbolAddress((void**)&p_wr,    g_wr);
    cudaGetSymbolAddress((void**)&p_qb,    g_qb);
    cudaGetSymbolAddress((void**)&p_kb,    g_kb);
    cudaGetSymbolAddress((void**)&p_part,  g_part);
    cudaGetSymbolAddress((void**)&p_cand,  g_cand);
    cudaGetSymbolAddress((void**)&p_topk,  g_topk);

    const float* cprojw_r = p_wr + W_CPROJ_OFF;
    const float* fcw_r    = p_wr + W_FC_OFF;
    const float* projw_r  = p_wr + W_PROJ_OFF;

    // 0. one-pass tf32 rounding of value-path weights
    roundw_kernel<<<(W_TOTAL / 4) / 256, 256>>>(cprojw, fcw, projw, p_wr);

    // 1. LN1 (exact — feeds selection-critical q path)
    ln_kernel<false><<<NTOK, 256>>>(prev, ln1g, ln1b, p_ln);

    // 2. q = LN1(x) @ c_attn_w[:, :768] + bias  (fp32 — preserves selection)
    sgemm_kernel<EPI_BIAS><<<dim3(DMODEL / 128, NTOK / 128), 256>>>(
        p_ln, DMODEL, cattnw, 3 * DMODEL, cattnb, nullptr, p_q, DMODEL, DMODEL);

    // 3. bf16 conversions (single launch)
    {
        int nq4 = NTOK * DMODEL / 4;
        int nk4 = MDB * DMODEL / 4;
        f2bf2_kernel<<<(nq4 + nk4) / 256, 256>>>(p_q, p_qb, dbk, p_kb, nq4);
    }

    // 4. bf16 mma.sync score GEMM + register top-16 (R6 config)
    int smem = 32768 + 128 * 132 * 4;  // 100352 B
    cudaFuncSetAttribute(score_topk_mma,
                         cudaFuncAttributeMaxDynamicSharedMemorySize, smem);
    score_topk_mma<<<dim3(NCH, NTOK / 128), 256, smem>>>(p_qb, p_kb, p_part);

    // 5. merge 128 packed candidates -> top-32 per token
    merge32_kernel<<<NTOK / 8, 256>>>(p_part, p_cand);

    // 6. exact fp32 rescore of top-32 -> final top-16 (jax tie-break)
    rescore_kernel<<<NTOK, 256>>>(p_q, dbk, p_cand, p_topk);

    // 7. per-token per-head softmax attention (output tf32-rounded)
    attn_kernel<<<NTOK, 384>>>(p_q, dbk, dbv, p_topk, p_attn);

    // 8. h = attn @ c_proj_w + bias + residual   (tf32, pre-rounded inputs)
    tgemm_kernel<EPI_BIAS_RES><<<dim3(DMODEL / 128, NTOK / 128), 256>>>(
        p_attn, DMODEL, cprojw_r, DMODEL, cprojb, prev, p_h, DMODEL, DMODEL);

    // 9. LN2 (output tf32-rounded — feeds fc GEMM only)
    ln_kernel<true><<<NTOK, 256>>>(p_h, ln2g, ln2b, p_ln);

    // 10. ff1 = gelu(LN2(h) @ fc_w + fc_b)       (tf32; gelu out rounded)
    tgemm_kernel<EPI_GELU><<<dim3(DFF / 128, NTOK / 128), 256>>>(
        p_ln, DMODEL, fcw_r, DFF, fcb, nullptr, p_ff1, DFF, DMODEL);

    // 11. out = ff1 @ proj_w + proj_b + h        (tf32)
    tgemm_kernel<EPI_BIAS_RES><<<dim3(DMODEL / 128, NTOK / 128), 256>>>(
        p_ff1, DFF, projw_r, DMODEL, projb, p_h, out, DMODEL, DFF);
}

// round 9
// speedup vs baseline: 1.4904x; 1.1637x over previous
#include <cuda_runtime.h>
#include <cuda_bf16.h>
#include <cuda_fp16.h>
#include <math_constants.h>
#include <cstdint>

#define NTOK   4096
#define DMODEL 768
#define NH     12
#define HD     64
#define KSEL   16
#define MDB    32768
#define NCH    8
#define CHUNK  (MDB/NCH)   /* 4096 keys per chunk */
#define DFF    3072
#define NCAND  32          /* rescored candidates per token */

#define W_CPROJ_OFF 0
#define W_FC_OFF    (DMODEL*DMODEL)
#define W_PROJ_OFF  (DMODEL*DMODEL + DMODEL*DFF)
#define W_TOTAL     (DMODEL*DMODEL + 2*DMODEL*DFF)   /* 5308416 */

// ---------------- scratch (device globals; no allocation allowed) ----------
__device__ float g_ln   [NTOK*DMODEL];
__device__ float g_q    [NTOK*DMODEL];
__device__ float g_h    [NTOK*DMODEL];
__device__ __half g_attnh[NTOK*DMODEL];
__device__ __half g_lnh  [NTOK*DMODEL];
__device__ __half g_ff1h [NTOK*DFF];
__device__ __half g_wh   [W_TOTAL];          // fp16 weights (c_proj|fc|proj)
__device__ __nv_bfloat16 g_qb[NTOK*DMODEL];
__device__ __nv_bfloat16 g_kb[MDB*DMODEL];
__device__ uint32_t g_part[NTOK*NCH*KSEL];   // packed (ord16<<16 | 4095-lidx)
__device__ int   g_cand  [NTOK*NCAND];
__device__ int   g_topk  [NTOK*KSEL];

// ---------------- helpers ---------------------------------------------------
__device__ __forceinline__ uint32_t smem_u32(const void* p) {
    uint32_t a;
    asm("{ .reg .u64 t; cvta.to.shared.u64 t, %1; cvt.u32.u64 %0, t; }" : "=r"(a) : "l"(p));
    return a;
}

__device__ __forceinline__ void ldsm_x4(uint32_t& r0, uint32_t& r1,
                                        uint32_t& r2, uint32_t& r3, uint32_t addr) {
    asm volatile("ldmatrix.sync.aligned.m8n8.x4.shared.b16 {%0,%1,%2,%3}, [%4];"
                 : "=r"(r0), "=r"(r1), "=r"(r2), "=r"(r3) : "r"(addr));
}
__device__ __forceinline__ void ldsm_x4t(uint32_t& r0, uint32_t& r1,
                                         uint32_t& r2, uint32_t& r3, uint32_t addr) {
    asm volatile("ldmatrix.sync.aligned.m8n8.x4.trans.shared.b16 {%0,%1,%2,%3}, [%4];"
                 : "=r"(r0), "=r"(r1), "=r"(r2), "=r"(r3) : "r"(addr));
}

__device__ __forceinline__ void mma16816(float* c, const uint32_t* a, const uint32_t* b) {
    asm("mma.sync.aligned.m16n8k16.row.col.f32.bf16.bf16.f32 "
        "{%0,%1,%2,%3}, {%4,%5,%6,%7}, {%8,%9}, {%0,%1,%2,%3};"
        : "+f"(c[0]), "+f"(c[1]), "+f"(c[2]), "+f"(c[3])
        : "r"(a[0]), "r"(a[1]), "r"(a[2]), "r"(a[3]), "r"(b[0]), "r"(b[1]));
}
__device__ __forceinline__ void mma16816h(float* c, const uint32_t* a, const uint32_t* b) {
    asm("mma.sync.aligned.m16n8k16.row.col.f32.f16.f16.f32 "
        "{%0,%1,%2,%3}, {%4,%5,%6,%7}, {%8,%9}, {%0,%1,%2,%3};"
        : "+f"(c[0]), "+f"(c[1]), "+f"(c[2]), "+f"(c[3])
        : "r"(a[0]), "r"(a[1]), "r"(a[2]), "r"(a[3]), "r"(b[0]), "r"(b[1]));
}

#define CP_ASYNC16(dst, src) \
    asm volatile("cp.async.cg.shared.global [%0], [%1], 16;" :: "r"(dst), "l"(src))
#define CP_COMMIT()  asm volatile("cp.async.commit_group;" ::: "memory")
#define CP_WAIT0()   asm volatile("cp.async.wait_group 0;" ::: "memory")

__device__ __forceinline__ float blockReduceSum(float v, float* red) {
    #pragma unroll
    for (int o = 16; o > 0; o >>= 1) v += __shfl_xor_sync(0xffffffffu, v, o);
    int w = threadIdx.x >> 5, l = threadIdx.x & 31;
    if (l == 0) red[w] = v;
    __syncthreads();
    if (w == 0) {
        float t = (l < 8) ? red[l] : 0.f;
        #pragma unroll
        for (int o = 4; o > 0; o >>= 1) t += __shfl_xor_sync(0xffffffffu, t, o);
        if (l == 0) red[0] = t;
    }
    __syncthreads();
    float r = red[0];
    __syncthreads();
    return r;
}

__device__ __forceinline__ float gelu_tanh(float x) {
    return 0.5f * x * (1.f + tanhf(0.7978845608028654f * (x + 0.044715f * x * x * x)));
}

__device__ __forceinline__ bool better(float s1, int i1, float s2, int i2) {
    return (s1 > s2) || (s1 == s2 && i1 < i2);
}

__device__ __forceinline__ uint32_t packkey(float s, int colLocal) {
    uint16_t b = __bfloat16_as_ushort(__float2bfloat16(s));
    uint16_t o = (b & 0x8000) ? (uint16_t)(~b) : (uint16_t)(b | 0x8000);
    return ((uint32_t)o << 16) | (uint32_t)(4095 - colLocal);
}

__device__ __forceinline__ void ins16(uint32_t& val, uint32_t k, int lane) {
    unsigned gt = __ballot_sync(0xffffffffu, k > val);
    uint32_t up = __shfl_up_sync(0xffffffffu, val, 1);
    if (gt) {
        int p = __ffs(gt) - 1;
        if (lane > p && lane < 16) val = up;
        if (lane == p) val = k;
    }
}

// ---------------- layernorm: fp32 out (LN1) / fp16 out (LN2) ----------------
__global__ __launch_bounds__(256) void ln_kernel(
    const float* __restrict__ x, const float* __restrict__ g,
    const float* __restrict__ b, float* __restrict__ y)
{
    __shared__ float red[8];
    int row = blockIdx.x;
    const float* xr = x + (size_t)row * DMODEL;
    int t = threadIdx.x;
    float v0 = xr[t], v1 = xr[t + 256], v2 = xr[t + 512];
    float mu = blockReduceSum(v0 + v1 + v2, red) * (1.f / DMODEL);
    float d0 = v0 - mu, d1 = v1 - mu, d2 = v2 - mu;
    float var = blockReduceSum(d0 * d0 + d1 * d1 + d2 * d2, red) * (1.f / DMODEL);
    float rs = rsqrtf(var + 1e-5f);
    float* yr = y + (size_t)row * DMODEL;
    yr[t]       = d0 * rs * g[t]       + b[t];
    yr[t + 256] = d1 * rs * g[t + 256] + b[t + 256];
    yr[t + 512] = d2 * rs * g[t + 512] + b[t + 512];
}

__global__ __launch_bounds__(256) void lnh_kernel(
    const float* __restrict__ x, const float* __restrict__ g,
    const float* __restrict__ b, __half* __restrict__ y)
{
    __shared__ float red[8];
    int row = blockIdx.x;
    const float* xr = x + (size_t)row * DMODEL;
    int t = threadIdx.x;
    float v0 = xr[t], v1 = xr[t + 256], v2 = xr[t + 512];
    float mu = blockReduceSum(v0 + v1 + v2, red) * (1.f / DMODEL);
    float d0 = v0 - mu, d1 = v1 - mu, d2 = v2 - mu;
    float var = blockReduceSum(d0 * d0 + d1 * d1 + d2 * d2, red) * (1.f / DMODEL);
    float rs = rsqrtf(var + 1e-5f);
    __half* yr = y + (size_t)row * DMODEL;
    yr[t]       = __float2half_rn(d0 * rs * g[t]       + b[t]);
    yr[t + 256] = __float2half_rn(d1 * rs * g[t + 256] + b[t + 256]);
    yr[t + 512] = __float2half_rn(d2 * rs * g[t + 512] + b[t + 512]);
}

// ---------------- combined fp32 -> bf16 convert (q then dbk) ----------------
__global__ __launch_bounds__(256) void f2bf2_kernel(
    const float* __restrict__ xq, __nv_bfloat16* __restrict__ yq,
    const float* __restrict__ xk, __nv_bfloat16* __restrict__ yk, int nq4)
{
    int i = blockIdx.x * 256 + threadIdx.x;
    const float* src; __nv_bfloat16* dst; int j;
    if (i < nq4) { src = xq; dst = yq; j = i; }
    else         { src = xk; dst = yk; j = i - nq4; }
    float4 v = reinterpret_cast<const float4*>(src)[j];
    __nv_bfloat162 a = __floats2bfloat162_rn(v.x, v.y);
    __nv_bfloat162 b = __floats2bfloat162_rn(v.z, v.w);
    reinterpret_cast<__nv_bfloat162*>(dst)[2 * j]     = a;
    reinterpret_cast<__nv_bfloat162*>(dst)[2 * j + 1] = b;
}

// ---------------- convert value-path weights to fp16 -------------------------
__global__ __launch_bounds__(256) void w2h_kernel(
    const float* __restrict__ w1, const float* __restrict__ w2,
    const float* __restrict__ w3, __half* __restrict__ dst)
{
    int i = blockIdx.x * 256 + threadIdx.x;       // float4 index
    const int n1 = (DMODEL * DMODEL) / 4;
    const int n2 = (DMODEL * DFF) / 4;
    const float* src; int j;
    if (i < n1)           { src = w1; j = i; }
    else if (i < n1 + n2) { src = w2; j = i - n1; }
    else                  { src = w3; j = i - n1 - n2; }
    float4 v = reinterpret_cast<const float4*>(src)[j];
    __half2 a = __floats2half2_rn(v.x, v.y);
    __half2 b = __floats2half2_rn(v.z, v.w);
    reinterpret_cast<__half2*>(dst)[2 * i]     = a;
    reinterpret_cast<__half2*>(dst)[2 * i + 1] = b;
}

// ---------------- fp32 SGEMM (only used for q; preserves selection) ---------
enum { EPI_BIAS = 0, EPI_BIAS_RES = 1, EPI_GELU = 2 };

template <int EPI>
__global__ __launch_bounds__(256) void sgemm_kernel(
    const float* __restrict__ A, int lda,
    const float* __restrict__ B, int ldb,
    const float* __restrict__ bias,
    const float* __restrict__ res,
    float* __restrict__ C, int ldc, int Kd)
{
    __shared__ float As[8][128];
    __shared__ float Bs[8][128];
    int tid  = threadIdx.x;
    int brow = blockIdx.y * 128, bcol = blockIdx.x * 128;
    int arow = tid >> 1, acol = (tid & 1) * 4;
    int bkr  = tid >> 5, bcol4 = (tid & 31) * 4;
    const float* Ap = A + (size_t)(brow + arow) * lda + acol;
    const float* Bp = B + (size_t)bkr * ldb + bcol + bcol4;
    int rbase = (tid >> 4) * 4, cbase = (tid & 15) * 4;

    float acc[8][8];
    #pragma unroll
    for (int i = 0; i < 8; i++)
        #pragma unroll
        for (int j = 0; j < 8; j++) acc[i][j] = 0.f;

    for (int k0 = 0; k0 < Kd; k0 += 8) {
        float4 av = *reinterpret_cast<const float4*>(Ap + k0);
        float4 bv = *reinterpret_cast<const float4*>(Bp + (size_t)k0 * ldb);
        __syncthreads();
        As[acol + 0][arow] = av.x; As[acol + 1][arow] = av.y;
        As[acol + 2][arow] = av.z; As[acol + 3][arow] = av.w;
        *reinterpret_cast<float4*>(&Bs[bkr][bcol4]) = bv;
        __syncthreads();
        #pragma unroll
        for (int kk = 0; kk < 8; kk++) {
            float a[8], bb[8];
            *reinterpret_cast<float4*>(a)      = *reinterpret_cast<const float4*>(&As[kk][rbase]);
            *reinterpret_cast<float4*>(a + 4)  = *reinterpret_cast<const float4*>(&As[kk][rbase + 64]);
            *reinterpret_cast<float4*>(bb)     = *reinterpret_cast<const float4*>(&Bs[kk][cbase]);
            *reinterpret_cast<float4*>(bb + 4) = *reinterpret_cast<const float4*>(&Bs[kk][cbase + 64]);
            #pragma unroll
            for (int i = 0; i < 8; i++)
                #pragma unroll
                for (int j = 0; j < 8; j++) acc[i][j] += a[i] * bb[j];
        }
    }

    #pragma unroll
    for (int i = 0; i < 8; i++) {
        int r = brow + rbase + ((i < 4) ? i : 60 + i);
        #pragma unroll
        for (int jg = 0; jg < 2; jg++) {
            int c = bcol + cbase + jg * 64;
            float4 bi = *reinterpret_cast<const float4*>(bias + c);
            float4 v;
            v.x = acc[i][jg * 4 + 0] + bi.x;
            v.y = acc[i][jg * 4 + 1] + bi.y;
            v.z = acc[i][jg * 4 + 2] + bi.z;
            v.w = acc[i][jg * 4 + 3] + bi.w;
            if (EPI == EPI_BIAS_RES) {
                float4 rv = *reinterpret_cast<const float4*>(res + (size_t)r * ldc + c);
                v.x += rv.x; v.y += rv.y; v.z += rv.z; v.w += rv.w;
            } else if (EPI == EPI_GELU) {
                v.x = gelu_tanh(v.x); v.y = gelu_tanh(v.y);
                v.z = gelu_tanh(v.z); v.w = gelu_tanh(v.w);
            }
            *reinterpret_cast<float4*>(C + (size_t)r * ldc + c) = v;
        }
    }
}

// ---------------- fp16 tensor-core GEMM (value path), cp.async pipelined ----
// C[M,N] = A[M,K]h @ B[K,N]h; 128x128 tile, K-panels of 64; 8 warps 2x4,
// warp tile 64x32 (R6-proven geometry). A frag: non-trans ldsm (score-kernel
// mapping). B frag: ldsm.x4.trans on [K][N] weight panel. fp32 accum.
// EPI_GELU writes __half C (feeds proj as A); EPI_BIAS_RES writes float C.
template <int EPI, typename CT>
__global__ __launch_bounds__(256, 2) void hgemm_kernel(
    const __half* __restrict__ A, int lda,
    const __half* __restrict__ B, int ldb,
    const float* __restrict__ bias,
    const float* __restrict__ res,
    CT* __restrict__ C, int ldc, int Kd)
{
    __shared__ __half Ash[2 * 8192];   // [buf][128 rows][64] swizzled 128B rows
    __shared__ __half Bsh[2 * 8192];   // [buf][64 rows][128] swizzled 256B rows
    uint32_t sA = smem_u32(Ash), sB = smem_u32(Bsh);
    int tid = threadIdx.x, lane = tid & 31, wid = tid >> 5;
    int warp_m = wid >> 2, warp_n = wid & 3;
    int brow = blockIdx.y * 128, bcol = blockIdx.x * 128;

    float acc[4][4][4];
    #pragma unroll
    for (int mt = 0; mt < 4; mt++)
        #pragma unroll
        for (int nt = 0; nt < 4; nt++)
            #pragma unroll
            for (int r = 0; r < 4; r++) acc[mt][nt][r] = 0.f;

    auto stageA = [&](int kp, int buf) {
        #pragma unroll
        for (int it = 0; it < 4; it++) {
            int id = tid + it * 256;       // 1024 chunks = 128 rows x 8 x 16B
            int row = id >> 3, col = id & 7;
            uint32_t d = sA + buf * 16384 + row * 128 + ((col ^ (row & 7)) << 4);
            const void* s = A + (size_t)(brow + row) * lda + kp + col * 8;
            CP_ASYNC16(d, s);
        }
    };
    auto stageB = [&](int kp, int buf) {
        #pragma unroll
        for (int it = 0; it < 4; it++) {
            int id = tid + it * 256;       // 1024 chunks = 64 rows x 16 x 16B
            int k = id >> 4, c = id & 15;
            uint32_t d = sB + buf * 16384 + k * 256 + ((c ^ (k & 7)) << 4);
            const void* s = B + (size_t)(kp + k) * ldb + bcol + c * 8;
            CP_ASYNC16(d, s);
        }
    };

    // A fragment addressing (non-trans ldsm, score-kernel mapping)
    uint32_t a_rel[4]; int a_rx[4];
    #pragma unroll
    for (int mt = 0; mt < 4; mt++) {
        int row = warp_m * 64 + mt * 16 + (lane & 15);
        a_rel[mt] = row * 128;
        a_rx[mt] = row & 7;
    }
    int a_ch = lane >> 4;

    // B fragment addressing (trans ldsm): lane -> matrix m, row r
    // k_local = (m&1)*8 + r; nchunk = warp_n*4 + g*2 + (m>>1)
    uint32_t b_off[2];
    {
        int m_ = lane >> 3, r_ = lane & 7;
        int kl = (m_ & 1) * 8 + r_;
        #pragma unroll
        for (int g = 0; g < 2; g++) {
            int nchunk = warp_n * 4 + g * 2 + (m_ >> 1);
            b_off[g] = kl * 256 + ((nchunk ^ (kl & 7)) << 4);
        }
    }

    stageA(0, 0); stageB(0, 0); CP_COMMIT();

    int npan = Kd / 64;
    for (int p = 0; p < npan; p++) {
        CP_WAIT0();
        __syncthreads();
        if (p + 1 < npan) {
            stageA((p + 1) * 64, (p + 1) & 1);
            stageB((p + 1) * 64, (p + 1) & 1);
            CP_COMMIT();
        }
        uint32_t abase = sA + (p & 1) * 16384;
        uint32_t bbase = sB + (p & 1) * 16384;

        #pragma unroll
        for (int kk = 0; kk < 4; kk++) {
            uint32_t af[4][4], bf[2][4];
            #pragma unroll
            for (int mt = 0; mt < 4; mt++) {
                int ch = kk * 2 + a_ch;
                ldsm_x4(af[mt][0], af[mt][1], af[mt][2], af[mt][3],
                        abase + a_rel[mt] + ((ch ^ a_rx[mt]) << 4));
            }
            #pragma unroll
            for (int g = 0; g < 2; g++)
                ldsm_x4t(bf[g][0], bf[g][1], bf[g][2], bf[g][3],
                         bbase + kk * 4096 + b_off[g]);
            #pragma unroll
            for (int mt = 0; mt < 4; mt++) {
                mma16816h(acc[mt][0], af[mt], &bf[0][0]);
                mma16816h(acc[mt][1], af[mt], &bf[0][2]);
                mma16816h(acc[mt][2], af[mt], &bf[1][0]);
                mma16816h(acc[mt][3], af[mt], &bf[1][2]);
            }
        }
    }

    // epilogue
    #pragma unroll
    for (int mt = 0; mt < 4; mt++) {
        #pragma unroll
        for (int rh = 0; rh < 2; rh++) {
            int r = brow + warp_m * 64 + mt * 16 + rh * 8 + (lane >> 2);
            #pragma unroll
            for (int nt = 0; nt < 4; nt++) {
                int c = bcol + warp_n * 32 + nt * 8 + 2 * (lane & 3);
                float vx = acc[mt][nt][rh * 2 + 0] + bias[c];
                float vy = acc[mt][nt][rh * 2 + 1] + bias[c + 1];
                if (EPI == EPI_BIAS_RES) {
                    float2 rv = *reinterpret_cast<const float2*>(res + (size_t)r * ldc + c);
                    vx += rv.x; vy += rv.y;
                } else if (EPI == EPI_GELU) {
                    vx = gelu_tanh(vx); vy = gelu_tanh(vy);
                }
                if (sizeof(CT) == 2) {
                    __half2 hv = __floats2half2_rn(vx, vy);
                    *reinterpret_cast<__half2*>((__half*)C + (size_t)r * ldc + c) = hv;
                } else {
                    *reinterpret_cast<float2*>((float*)C + (size_t)r * ldc + c) =
                        make_float2(vx, vy);
                }
            }
        }
    }
}

// ---------------- bf16 mma.sync score GEMM + register top-16 (R6 proven) ----
#define SC_SC 32768

__device__ __forceinline__ void stage64_async(
    uint32_t dstb, const __nv_bfloat16* __restrict__ src, int tid)
{
    #pragma unroll
    for (int it = 0; it < 4; it++) {
        int c = tid + it * 256;          // 1024 chunks = 128 rows x 8 x 16B
        int row = c >> 3, col = c & 7;
        uint32_t d = dstb + row * 128 + ((col ^ (row & 7)) << 4);
        const void* s = src + (size_t)row * DMODEL + col * 8;
        CP_ASYNC16(d, s);
    }
}

__global__ __launch_bounds__(256, 2) void score_topk_mma(
    const __nv_bfloat16* __restrict__ qb, const __nv_bfloat16* __restrict__ kb,
    uint32_t* __restrict__ part)
{
    extern __shared__ char dsm[];
    uint32_t (*Sc)[132] = (uint32_t(*)[132])(dsm + SC_SC);
    uint32_t sbase = smem_u32(dsm);

    int tid = threadIdx.x, lane = tid & 31, wid = tid >> 5;
    int warp_m = wid >> 2, warp_n = wid & 3;
    int q0 = blockIdx.y * 128;
    int c0 = blockIdx.x * CHUNK;

    uint32_t lst[16];
    #pragma unroll
    for (int r = 0; r < 16; r++) lst[r] = (lane < 16) ? 0u : 0xffffffffu;

    uint32_t a_rel[4], b_rel[2];
    int a_rx[4], b_rx[2];
    #pragma unroll
    for (int mt = 0; mt < 4; mt++) {
        int row = warp_m * 64 + mt * 16 + (lane & 15);
        a_rel[mt] = row * 128;
        a_rx[mt] = row & 7;
    }
    #pragma unroll
    for (int pr = 0; pr < 2; pr++) {
        int row = warp_n * 32 + pr * 16 + (lane & 7) + ((lane >> 4) << 3);
        b_rel[pr] = row * 128;
        b_rx[pr] = row & 7;
    }
    int a_ch = lane >> 4;
    int b_ch = (lane >> 3) & 1;

    const __nv_bfloat16* qbase = qb + (size_t)q0 * DMODEL;

    stage64_async(sbase,         qbase, tid);
    stage64_async(sbase + 16384, kb + (size_t)c0 * DMODEL, tid);
    CP_COMMIT();

    for (int kt = 0; kt < CHUNK / 128; kt++) {
        int kb0 = c0 + kt * 128;
        const __nv_bfloat16* kbase = kb + (size_t)kb0 * DMODEL;

        float acc[4][4][4];
        #pragma unroll
        for (int mt = 0; mt < 4; mt++)
            #pragma unroll
            for (int nt = 0; nt < 4; nt++)
                #pragma unroll
                for (int r = 0; r < 4; r++) acc[mt][nt][r] = 0.f;

        for (int kc = 0; kc < DMODEL / 64; kc++) {
            CP_WAIT0();
            __syncthreads();
            if (kc + 1 < DMODEL / 64) {
                uint32_t nb = sbase + ((kc + 1) & 1) * 32768;
                stage64_async(nb,         qbase + (kc + 1) * 64, tid);
                stage64_async(nb + 16384, kbase + (kc + 1) * 64, tid);
                CP_COMMIT();
            }
            uint32_t abase = sbase + (kc & 1) * 32768;
            uint32_t bbase = abase + 16384;

            #pragma unroll
            for (int kk = 0; kk < 4; kk++) {
                uint32_t af[4][4], bf[2][4];
                #pragma unroll
                for (int mt = 0; mt < 4; mt++) {
                    int ch = kk * 2 + a_ch;
                    ldsm_x4(af[mt][0], af[mt][1], af[mt][2], af[mt][3],
                            abase + a_rel[mt] + ((ch ^ a_rx[mt]) << 4));
                }
                #pragma unroll
                for (int pr = 0; pr < 2; pr++) {
                    int ch = kk * 2 + b_ch;
                    ldsm_x4(bf[pr][0], bf[pr][1], bf[pr][2], bf[pr][3],
                            bbase + b_rel[pr] + ((ch ^ b_rx[pr]) << 4));
                }
                #pragma unroll
                for (int mt = 0; mt < 4; mt++) {
                    mma16816(acc[mt][0], af[mt], &bf[0][0]);
                    mma16816(acc[mt][1], af[mt], &bf[0][2]);
                    mma16816(acc[mt][2], af[mt], &bf[1][0]);
                    mma16816(acc[mt][3], af[mt], &bf[1][2]);
                }
            }
        }

        __syncthreads();
        #pragma unroll
        for (int mt = 0; mt < 4; mt++) {
            int r = warp_m * 64 + mt * 16 + (lane >> 2);
            #pragma unroll
            for (int nt = 0; nt < 4; nt++) {
                int c = warp_n * 32 + nt * 8 + 2 * (lane & 3);
                int cl = kt * 128 + c;
                uint2 k0 = make_uint2(packkey(acc[mt][nt][0], cl),
                                      packkey(acc[mt][nt][1], cl + 1));
                uint2 k1 = make_uint2(packkey(acc[mt][nt][2], cl),
                                      packkey(acc[mt][nt][3], cl + 1));
                *reinterpret_cast<uint2*>(&Sc[r][c])     = k0;
                *reinterpret_cast<uint2*>(&Sc[r + 8][c]) = k1;
            }
        }
        __syncthreads();

        if (kt + 1 < CHUNK / 128) {
            stage64_async(sbase,         qbase, tid);
            stage64_async(sbase + 16384, kb + (size_t)(kb0 + 128) * DMODEL, tid);
            CP_COMMIT();
        }

        #pragma unroll
        for (int r = 0; r < 16; r++) {
            int row = wid * 16 + r;
            uint4 kv = *reinterpret_cast<const uint4*>(&Sc[row][lane * 4]);
            uint32_t thr = __shfl_sync(0xffffffffu, lst[r], 15);
            bool c = (kv.x > thr) | (kv.y > thr) | (kv.z > thr) | (kv.w > thr);
            unsigned m = __ballot_sync(0xffffffffu, c);
            while (m) {
                int src = __ffs(m) - 1; m &= m - 1;
                uint32_t k0 = __shfl_sync(0xffffffffu, kv.x, src);
                uint32_t k1 = __shfl_sync(0xffffffffu, kv.y, src);
                uint32_t k2 = __shfl_sync(0xffffffffu, kv.z, src);
                uint32_t k3 = __shfl_sync(0xffffffffu, kv.w, src);
                thr = __shfl_sync(0xffffffffu, lst[r], 15);
                if (k0 > thr) { ins16(lst[r], k0, lane); thr = __shfl_sync(0xffffffffu, lst[r], 15); }
                if (k1 > thr) { ins16(lst[r], k1, lane); thr = __shfl_sync(0xffffffffu, lst[r], 15); }
                if (k2 > thr) { ins16(lst[r], k2, lane); thr = __shfl_sync(0xffffffffu, lst[r], 15); }
                if (k3 > thr) { ins16(lst[r], k3, lane); }
            }
        }
        __syncthreads();
    }

    if (lane < 16) {
        #pragma unroll
        for (int r = 0; r < 16; r++) {
            int row = q0 + wid * 16 + r;
            part[((size_t)row * NCH + blockIdx.x) * KSEL + lane] = lst[r];
        }
    }
}

// ---------------- merge 128 packed candidates/row -> top-32 -----------------
__global__ __launch_bounds__(256) void merge32_kernel(
    const uint32_t* __restrict__ part, int* __restrict__ cand)
{
    int lane = threadIdx.x & 31;
    int row  = blockIdx.x * 8 + (threadIdx.x >> 5);
    unsigned long long mk[4];
    #pragma unroll
    for (int j = 0; j < 4; j++) {
        int e = lane + 32 * j;
        uint32_t key = part[(size_t)row * 128 + e];
        int gid = (e >> 4) * CHUNK + 4095 - (int)(key & 0xfffu);
        mk[j] = ((unsigned long long)(key >> 16) << 32) | (uint32_t)(0xffffffffu - gid);
    }
    for (int t = 0; t < NCAND; t++) {
        unsigned long long best = mk[0];
        #pragma unroll
        for (int j = 1; j < 4; j++) if (mk[j] > best) best = mk[j];
        #pragma unroll
        for (int o = 16; o > 0; o >>= 1) {
            unsigned long long ob = __shfl_xor_sync(0xffffffffu, best, o);
            if (ob > best) best = ob;
        }
        if (lane == 0)
            cand[row * NCAND + t] = (int)(0xffffffffu - (uint32_t)best);
        #pragma unroll
        for (int j = 0; j < 4; j++) if (mk[j] == best) mk[j] = 0;
    }
}

// ---------------- exact fp32 rescore of 32 candidates -> final top-16 -------
__global__ __launch_bounds__(256) void rescore_kernel(
    const float* __restrict__ q, const float* __restrict__ dbk,
    const int* __restrict__ cand, int* __restrict__ topk)
{
    __shared__ float sq[DMODEL];
    __shared__ float ss[NCAND];
    __shared__ int   sid[NCAND];
    int t = blockIdx.x, tid = threadIdx.x;
    int w = tid >> 5, lane = tid & 31;
    sq[tid]       = q[(size_t)t * DMODEL + tid];
    sq[tid + 256] = q[(size_t)t * DMODEL + tid + 256];
    sq[tid + 512] = q[(size_t)t * DMODEL + tid + 512];
    if (tid < NCAND) sid[tid] = cand[t * NCAND + tid];
    __syncthreads();

    for (int cc = w; cc < NCAND; cc += 8) {
        const float* kr = dbk + (size_t)sid[cc] * DMODEL;
        float p = 0.f;
        #pragma unroll
        for (int j = 0; j < DMODEL / 32; j++)
            p += sq[lane + 32 * j] * kr[lane + 32 * j];
        #pragma unroll
        for (int o = 16; o > 0; o >>= 1) p += __shfl_xor_sync(0xffffffffu, p, o);
        if (lane == 0) ss[cc] = p;
    }
    __syncthreads();

    if (w == 0) {
        float s = ss[lane];
        int  id = sid[lane];
        for (int it = 0; it < KSEL; it++) {
            float bs = s; int bid = id;
            #pragma unroll
            for (int o = 16; o > 0; o >>= 1) {
                float os = __shfl_xor_sync(0xffffffffu, bs, o);
                int   oi = __shfl_xor_sync(0xffffffffu, bid, o);
                if (better(os, oi, bs, bid)) { bs = os; bid = oi; }
            }
            if (lane == 0) topk[t * KSEL + it] = bid;
            if (id == bid) { s = -CUDART_INF_F; id = 0x7fffffff; }
        }
    }
}

// ---------------- per-token memory attention (fp16 output) ------------------
__global__ __launch_bounds__(384) void attn_kernel(
    const float* __restrict__ q, const float* __restrict__ dbk,
    const float* __restrict__ dbv, const int* __restrict__ topk,
    __half* __restrict__ out)
{
    __shared__ float sq[DMODEL];
    __shared__ int   sidx[KSEL];
    __shared__ float saw[NH][KSEL];
    int t = blockIdx.x;
    int tid = threadIdx.x, lane = tid & 31, w = tid >> 5;
    sq[tid]       = q[(size_t)t * DMODEL + tid];
    sq[tid + 384] = q[(size_t)t * DMODEL + tid + 384];
    if (tid < KSEL) sidx[tid] = topk[t * KSEL + tid];
    __syncthreads();

    float q1 = sq[w * HD + lane], q2 = sq[w * HD + lane + 32];
    for (int m = 0; m < KSEL; m++) {
        const float* kr = dbk + (size_t)sidx[m] * DMODEL + w * HD;
        float p = q1 * kr[lane] + q2 * kr[lane + 32];
        #pragma unroll
        for (int o = 16; o > 0; o >>= 1) p += __shfl_xor_sync(0xffffffffu, p, o);
        if (lane == 0) saw[w][m] = p * 0.125f;
    }
    __syncwarp();
    {
        float x = (lane < KSEL) ? saw[w][lane] : -CUDART_INF_F;
        float mx = x;
        #pragma unroll
        for (int o = 16; o > 0; o >>= 1) mx = fmaxf(mx, __shfl_xor_sync(0xffffffffu, mx, o));
        float e = (lane < KSEL) ? expf(x - mx) : 0.f;
        float se = e;
        #pragma unroll
        for (int o = 16; o > 0; o >>= 1) se += __shfl_xor_sync(0xffffffffu, se, o);
        if (lane < KSEL) saw[w][lane] = e / se;
    }
    __syncwarp();
    float a1 = 0.f, a2 = 0.f;
    for (int m = 0; m < KSEL; m++) {
        float aw = saw[w][m];
        const float* vr = dbv + (size_t)sidx[m] * DMODEL + w * HD;
        a1 += aw * vr[lane]; a2 += aw * vr[lane + 32];
    }
    out[(size_t)t * DMODEL + w * HD + lane]      = __float2half_rn(a1);
    out[(size_t)t * DMODEL + w * HD + lane + 32] = __float2half_rn(a2);
}

// ---------------- launch -----------------------------------------------------
extern "C" void kernel_launch(void* const* d_in, const int* in_sizes, int n_in,
                              void* d_out, int out_size)
{
    const float* prev   = (const float*)d_in[0];
    const float* dbk    = (const float*)d_in[1];
    const float* dbv    = (const float*)d_in[2];
    const float* ln1g   = (const float*)d_in[3];
    const float* ln1b   = (const float*)d_in[4];
    const float* cattnw = (const float*)d_in[5];
    const float* cattnb = (const float*)d_in[6];
    const float* cprojw = (const float*)d_in[7];
    const float* cprojb = (const float*)d_in[8];
    const float* ln2g   = (const float*)d_in[9];
    const float* ln2b   = (const float*)d_in[10];
    const float* fcw    = (const float*)d_in[11];
    const float* fcb    = (const float*)d_in[12];
    const float* projw  = (const float*)d_in[13];
    const float* projb  = (const float*)d_in[14];
    float* out = (float*)d_out;

    float *p_ln, *p_q, *p_h;
    __half *p_attnh, *p_lnh, *p_ff1h, *p_wh;
    __nv_bfloat16 *p_qb, *p_kb;
    uint32_t *p_part;
    int *p_cand, *p_topk;
    cudaGetSymbolAddress((void**)&p_ln,    g_ln);
    cudaGetSymbolAddress((void**)&p_q,     g_q);
    cudaGetSymbolAddress((void**)&p_h,     g_h);
    cudaGetSymbolAddress((void**)&p_attnh, g_attnh);
    cudaGetSymbolAddress((void**)&p_lnh,   g_lnh);
    cudaGetSymbolAddress((void**)&p_ff1h,  g_ff1h);
    cudaGetSymbolAddress((void**)&p_wh,    g_wh);
    cudaGetSymbolAddress((void**)&p_qb,    g_qb);
    cudaGetSymbolAddress((void**)&p_kb,    g_kb);
    cudaGetSymbolAddress((void**)&p_part,  g_part);
    cudaGetSymbolAddress((void**)&p_cand,  g_cand);
    cudaGetSymbolAddress((void**)&p_topk,  g_topk);

    const __half* cprojw_h = p_wh + W_CPROJ_OFF;
    const __half* fcw_h    = p_wh + W_FC_OFF;
    const __half* projw_h  = p_wh + W_PROJ_OFF;

    // 0. one-pass fp16 conversion of value-path weights
    w2h_kernel<<<(W_TOTAL / 4) / 256, 256>>>(cprojw, fcw, projw, p_wh);

    // 1. LN1 (exact fp32 — feeds selection-critical q path)
    ln_kernel<<<NTOK, 256>>>(prev, ln1g, ln1b, p_ln);

    // 2. q = LN1(x) @ c_attn_w[:, :768] + bias  (fp32 — preserves selection)
    sgemm_kernel<EPI_BIAS><<<dim3(DMODEL / 128, NTOK / 128), 256>>>(
        p_ln, DMODEL, cattnw, 3 * DMODEL, cattnb, nullptr, p_q, DMODEL, DMODEL);

    // 3. bf16 conversions (single launch)
    {
        int nq4 = NTOK * DMODEL / 4;
        int nk4 = MDB * DMODEL / 4;
        f2bf2_kernel<<<(nq4 + nk4) / 256, 256>>>(p_q, p_qb, dbk, p_kb, nq4);
    }

    // 4. bf16 mma.sync score GEMM + register top-16 (R6 config)
    int smem = 32768 + 128 * 132 * 4;  // 100352 B
    cudaFuncSetAttribute(score_topk_mma,
                         cudaFuncAttributeMaxDynamicSharedMemorySize, smem);
    score_topk_mma<<<dim3(NCH, NTOK / 128), 256, smem>>>(p_qb, p_kb, p_part);

    // 5. merge 128 packed candidates -> top-32 per token
    merge32_kernel<<<NTOK / 8, 256>>>(p_part, p_cand);

    // 6. exact fp32 rescore of top-32 -> final top-16 (jax tie-break)
    rescore_kernel<<<NTOK, 256>>>(p_q, dbk, p_cand, p_topk);

    // 7. per-token per-head softmax attention (fp16 output)
    attn_kernel<<<NTOK, 384>>>(p_q, dbk, dbv, p_topk, p_attnh);

    // 8. h = attn @ c_proj_w + bias + residual   (fp16 tensor cores, fp32 out)
    hgemm_kernel<EPI_BIAS_RES, float><<<dim3(DMODEL / 128, NTOK / 128), 256>>>(
        p_attnh, DMODEL, cprojw_h, DMODEL, cprojb, prev, p_h, DMODEL, DMODEL);

    // 9. LN2 (fp16 output — feeds fc GEMM only)
    lnh_kernel<<<NTOK, 256>>>(p_h, ln2g, ln2b, p_lnh);

    // 10. ff1 = gelu(LN2(h) @ fc_w + fc_b)       (fp16; half output)
    hgemm_kernel<EPI_GELU, __half><<<dim3(DFF / 128, NTOK / 128), 256>>>(
        p_lnh, DMODEL, fcw_h, DFF, fcb, nullptr, p_ff1h, DFF, DMODEL);

    // 11. out = ff1 @ proj_w + proj_b + h        (fp16, fp32 out)
    hgemm_kernel<EPI_BIAS_RES, float><<<dim3(DMODEL / 128, NTOK / 128), 256>>>(
        p_ff1h, DFF, projw_h, DMODEL, projb, p_h, out, DMODEL, DFF);
}

// round 10
// speedup vs baseline: 1.4942x; 1.0026x over previous
#include <cuda_runtime.h>
#include <cuda_bf16.h>
#include <cuda_fp16.h>
#include <math_constants.h>
#include <cstdint>

#define NTOK   4096
#define DMODEL 768
#define NH     12
#define HD     64
#define KSEL   16
#define MDB    32768
#define NCH    8
#define CHUNK  (MDB/NCH)   /* 4096 keys per chunk */
#define DFF    3072
#define NCAND  32          /* rescored candidates per token */

#define W_CPROJ_OFF 0
#define W_FC_OFF    (DMODEL*DMODEL)
#define W_PROJ_OFF  (DMODEL*DMODEL + DMODEL*DFF)
#define W_TOTAL     (DMODEL*DMODEL + 2*DMODEL*DFF)   /* 5308416 */

// ---------------- scratch (device globals; no allocation allowed) ----------
__device__ float g_ln   [NTOK*DMODEL];
__device__ float g_q    [NTOK*DMODEL];
__device__ float g_h    [NTOK*DMODEL];
__device__ __half g_attnh[NTOK*DMODEL];
__device__ __half g_lnh  [NTOK*DMODEL];
__device__ __half g_ff1h [NTOK*DFF];
__device__ __half g_wh   [W_TOTAL];          // fp16 weights (c_proj|fc|proj)
__device__ __nv_bfloat16 g_qb[NTOK*DMODEL];
__device__ __nv_bfloat16 g_kb[MDB*DMODEL];
__device__ uint32_t g_part[NTOK*NCH*KSEL];   // packed (ord16<<16 | 4095-lidx)
__device__ int   g_cand  [NTOK*NCAND];
__device__ int   g_topk  [NTOK*KSEL];

// ---------------- helpers ---------------------------------------------------
__device__ __forceinline__ uint32_t smem_u32(const void* p) {
    uint32_t a;
    asm("{ .reg .u64 t; cvta.to.shared.u64 t, %1; cvt.u32.u64 %0, t; }" : "=r"(a) : "l"(p));
    return a;
}

__device__ __forceinline__ void ldsm_x4(uint32_t& r0, uint32_t& r1,
                                        uint32_t& r2, uint32_t& r3, uint32_t addr) {
    asm volatile("ldmatrix.sync.aligned.m8n8.x4.shared.b16 {%0,%1,%2,%3}, [%4];"
                 : "=r"(r0), "=r"(r1), "=r"(r2), "=r"(r3) : "r"(addr));
}
__device__ __forceinline__ void ldsm_x4t(uint32_t& r0, uint32_t& r1,
                                         uint32_t& r2, uint32_t& r3, uint32_t addr) {
    asm volatile("ldmatrix.sync.aligned.m8n8.x4.trans.shared.b16 {%0,%1,%2,%3}, [%4];"
                 : "=r"(r0), "=r"(r1), "=r"(r2), "=r"(r3) : "r"(addr));
}

__device__ __forceinline__ void mma16816(float* c, const uint32_t* a, const uint32_t* b) {
    asm("mma.sync.aligned.m16n8k16.row.col.f32.bf16.bf16.f32 "
        "{%0,%1,%2,%3}, {%4,%5,%6,%7}, {%8,%9}, {%0,%1,%2,%3};"
        : "+f"(c[0]), "+f"(c[1]), "+f"(c[2]), "+f"(c[3])
        : "r"(a[0]), "r"(a[1]), "r"(a[2]), "r"(a[3]), "r"(b[0]), "r"(b[1]));
}
__device__ __forceinline__ void mma16816h(float* c, const uint32_t* a, const uint32_t* b) {
    asm("mma.sync.aligned.m16n8k16.row.col.f32.f16.f16.f32 "
        "{%0,%1,%2,%3}, {%4,%5,%6,%7}, {%8,%9}, {%0,%1,%2,%3};"
        : "+f"(c[0]), "+f"(c[1]), "+f"(c[2]), "+f"(c[3])
        : "r"(a[0]), "r"(a[1]), "r"(a[2]), "r"(a[3]), "r"(b[0]), "r"(b[1]));
}

// packed dual fp32 FMA (Blackwell f32x2; each lane exact rn fp32 FMA)
__device__ __forceinline__ void fma_f32x2(unsigned long long& acc,
                                          unsigned long long a,
                                          unsigned long long b) {
    asm("fma.rn.f32x2 %0, %1, %2, %0;" : "+l"(acc) : "l"(a), "l"(b));
}
__device__ __forceinline__ unsigned long long dup_f32x2(float x) {
    unsigned long long r;
    uint32_t u = __float_as_uint(x);
    asm("mov.b64 %0, {%1, %1};" : "=l"(r) : "r"(u));
    return r;
}
__device__ __forceinline__ float2 unpack_f32x2(unsigned long long v) {
    uint32_t lo, hi;
    asm("mov.b64 {%0, %1}, %2;" : "=r"(lo), "=r"(hi) : "l"(v));
    return make_float2(__uint_as_float(lo), __uint_as_float(hi));
}

#define CP_ASYNC16(dst, src) \
    asm volatile("cp.async.cg.shared.global [%0], [%1], 16;" :: "r"(dst), "l"(src))
#define CP_COMMIT()  asm volatile("cp.async.commit_group;" ::: "memory")
#define CP_WAIT0()   asm volatile("cp.async.wait_group 0;" ::: "memory")

__device__ __forceinline__ float blockReduceSum(float v, float* red) {
    #pragma unroll
    for (int o = 16; o > 0; o >>= 1) v += __shfl_xor_sync(0xffffffffu, v, o);
    int w = threadIdx.x >> 5, l = threadIdx.x & 31;
    if (l == 0) red[w] = v;
    __syncthreads();
    if (w == 0) {
        float t = (l < 8) ? red[l] : 0.f;
        #pragma unroll
        for (int o = 4; o > 0; o >>= 1) t += __shfl_xor_sync(0xffffffffu, t, o);
        if (l == 0) red[0] = t;
    }
    __syncthreads();
    float r = red[0];
    __syncthreads();
    return r;
}

__device__ __forceinline__ float gelu_tanh(float x) {
    return 0.5f * x * (1.f + tanhf(0.7978845608028654f * (x + 0.044715f * x * x * x)));
}

__device__ __forceinline__ bool better(float s1, int i1, float s2, int i2) {
    return (s1 > s2) || (s1 == s2 && i1 < i2);
}

__device__ __forceinline__ uint32_t packkey(float s, int colLocal) {
    uint16_t b = __bfloat16_as_ushort(__float2bfloat16(s));
    uint16_t o = (b & 0x8000) ? (uint16_t)(~b) : (uint16_t)(b | 0x8000);
    return ((uint32_t)o << 16) | (uint32_t)(4095 - colLocal);
}

__device__ __forceinline__ void ins16(uint32_t& val, uint32_t k, int lane) {
    unsigned gt = __ballot_sync(0xffffffffu, k > val);
    uint32_t up = __shfl_up_sync(0xffffffffu, val, 1);
    if (gt) {
        int p = __ffs(gt) - 1;
        if (lane > p && lane < 16) val = up;
        if (lane == p) val = k;
    }
}

// ---------------- layernorm: fp32 out (LN1) / fp16 out (LN2) ----------------
__global__ __launch_bounds__(256) void ln_kernel(
    const float* __restrict__ x, const float* __restrict__ g,
    const float* __restrict__ b, float* __restrict__ y)
{
    __shared__ float red[8];
    int row = blockIdx.x;
    const float* xr = x + (size_t)row * DMODEL;
    int t = threadIdx.x;
    float v0 = xr[t], v1 = xr[t + 256], v2 = xr[t + 512];
    float mu = blockReduceSum(v0 + v1 + v2, red) * (1.f / DMODEL);
    float d0 = v0 - mu, d1 = v1 - mu, d2 = v2 - mu;
    float var = blockReduceSum(d0 * d0 + d1 * d1 + d2 * d2, red) * (1.f / DMODEL);
    float rs = rsqrtf(var + 1e-5f);
    float* yr = y + (size_t)row * DMODEL;
    yr[t]       = d0 * rs * g[t]       + b[t];
    yr[t + 256] = d1 * rs * g[t + 256] + b[t + 256];
    yr[t + 512] = d2 * rs * g[t + 512] + b[t + 512];
}

__global__ __launch_bounds__(256) void lnh_kernel(
    const float* __restrict__ x, const float* __restrict__ g,
    const float* __restrict__ b, __half* __restrict__ y)
{
    __shared__ float red[8];
    int row = blockIdx.x;
    const float* xr = x + (size_t)row * DMODEL;
    int t = threadIdx.x;
    float v0 = xr[t], v1 = xr[t + 256], v2 = xr[t + 512];
    float mu = blockReduceSum(v0 + v1 + v2, red) * (1.f / DMODEL);
    float d0 = v0 - mu, d1 = v1 - mu, d2 = v2 - mu;
    float var = blockReduceSum(d0 * d0 + d1 * d1 + d2 * d2, red) * (1.f / DMODEL);
    float rs = rsqrtf(var + 1e-5f);
    __half* yr = y + (size_t)row * DMODEL;
    yr[t]       = __float2half_rn(d0 * rs * g[t]       + b[t]);
    yr[t + 256] = __float2half_rn(d1 * rs * g[t + 256] + b[t + 256]);
    yr[t + 512] = __float2half_rn(d2 * rs * g[t + 512] + b[t + 512]);
}

// ---------------- combined fp32 -> bf16 convert (q then dbk) ----------------
__global__ __launch_bounds__(256) void f2bf2_kernel(
    const float* __restrict__ xq, __nv_bfloat16* __restrict__ yq,
    const float* __restrict__ xk, __nv_bfloat16* __restrict__ yk, int nq4)
{
    int i = blockIdx.x * 256 + threadIdx.x;
    const float* src; __nv_bfloat16* dst; int j;
    if (i < nq4) { src = xq; dst = yq; j = i; }
    else         { src = xk; dst = yk; j = i - nq4; }
    float4 v = reinterpret_cast<const float4*>(src)[j];
    __nv_bfloat162 a = __floats2bfloat162_rn(v.x, v.y);
    __nv_bfloat162 b = __floats2bfloat162_rn(v.z, v.w);
    reinterpret_cast<__nv_bfloat162*>(dst)[2 * j]     = a;
    reinterpret_cast<__nv_bfloat162*>(dst)[2 * j + 1] = b;
}

// ---------------- convert value-path weights to fp16 -------------------------
__global__ __launch_bounds__(256) void w2h_kernel(
    const float* __restrict__ w1, const float* __restrict__ w2,
    const float* __restrict__ w3, __half* __restrict__ dst)
{
    int i = blockIdx.x * 256 + threadIdx.x;       // float4 index
    const int n1 = (DMODEL * DMODEL) / 4;
    const int n2 = (DMODEL * DFF) / 4;
    const float* src; int j;
    if (i < n1)           { src = w1; j = i; }
    else if (i < n1 + n2) { src = w2; j = i - n1; }
    else                  { src = w3; j = i - n1 - n2; }
    float4 v = reinterpret_cast<const float4*>(src)[j];
    __half2 a = __floats2half2_rn(v.x, v.y);
    __half2 b = __floats2half2_rn(v.z, v.w);
    reinterpret_cast<__half2*>(dst)[2 * i]     = a;
    reinterpret_cast<__half2*>(dst)[2 * i + 1] = b;
}

// ---------------- fp32 SGEMM via packed f32x2 FMA (q path; exact fp32) ------
enum { EPI_BIAS = 0, EPI_BIAS_RES = 1, EPI_GELU = 2 };

template <int EPI>
__global__ __launch_bounds__(256) void sgemm_kernel(
    const float* __restrict__ A, int lda,
    const float* __restrict__ B, int ldb,
    const float* __restrict__ bias,
    const float* __restrict__ res,
    float* __restrict__ C, int ldc, int Kd)
{
    __shared__ float As[8][128];
    __shared__ float Bs[8][128];
    int tid  = threadIdx.x;
    int brow = blockIdx.y * 128, bcol = blockIdx.x * 128;
    int arow = tid >> 1, acol = (tid & 1) * 4;
    int bkr  = tid >> 5, bcol4 = (tid & 31) * 4;
    const float* Ap = A + (size_t)(brow + arow) * lda + acol;
    const float* Bp = B + (size_t)bkr * ldb + bcol + bcol4;
    int rbase = (tid >> 4) * 4, cbase = (tid & 15) * 4;

    // packed accumulators: acc[i][j] holds columns (2j, 2j+1) of micro-col
    unsigned long long acc[8][4];
    #pragma unroll
    for (int i = 0; i < 8; i++)
        #pragma unroll
        for (int j = 0; j < 4; j++) acc[i][j] = 0ull;

    for (int k0 = 0; k0 < Kd; k0 += 8) {
        float4 av = *reinterpret_cast<const float4*>(Ap + k0);
        float4 bv = *reinterpret_cast<const float4*>(Bp + (size_t)k0 * ldb);
        __syncthreads();
        As[acol + 0][arow] = av.x; As[acol + 1][arow] = av.y;
        As[acol + 2][arow] = av.z; As[acol + 3][arow] = av.w;
        *reinterpret_cast<float4*>(&Bs[bkr][bcol4]) = bv;
        __syncthreads();
        #pragma unroll
        for (int kk = 0; kk < 8; kk++) {
            float a[8];
            *reinterpret_cast<float4*>(a)      = *reinterpret_cast<const float4*>(&As[kk][rbase]);
            *reinterpret_cast<float4*>(a + 4)  = *reinterpret_cast<const float4*>(&As[kk][rbase + 64]);
            ulonglong2 b01 = *reinterpret_cast<const ulonglong2*>(&Bs[kk][cbase]);
            ulonglong2 b23 = *reinterpret_cast<const ulonglong2*>(&Bs[kk][cbase + 64]);
            #pragma unroll
            for (int i = 0; i < 8; i++) {
                unsigned long long ap = dup_f32x2(a[i]);
                fma_f32x2(acc[i][0], ap, b01.x);
                fma_f32x2(acc[i][1], ap, b01.y);
                fma_f32x2(acc[i][2], ap, b23.x);
                fma_f32x2(acc[i][3], ap, b23.y);
            }
        }
    }

    #pragma unroll
    for (int i = 0; i < 8; i++) {
        int r = brow + rbase + ((i < 4) ? i : 60 + i);
        #pragma unroll
        for (int jg = 0; jg < 2; jg++) {
            int c = bcol + cbase + jg * 64;
            float2 p0 = unpack_f32x2(acc[i][jg * 2 + 0]);
            float2 p1 = unpack_f32x2(acc[i][jg * 2 + 1]);
            float4 bi = *reinterpret_cast<const float4*>(bias + c);
            float4 v;
            v.x = p0.x + bi.x;
            v.y = p0.y + bi.y;
            v.z = p1.x + bi.z;
            v.w = p1.y + bi.w;
            if (EPI == EPI_BIAS_RES) {
                float4 rv = *reinterpret_cast<const float4*>(res + (size_t)r * ldc + c);
                v.x += rv.x; v.y += rv.y; v.z += rv.z; v.w += rv.w;
            } else if (EPI == EPI_GELU) {
                v.x = gelu_tanh(v.x); v.y = gelu_tanh(v.y);
                v.z = gelu_tanh(v.z); v.w = gelu_tanh(v.w);
            }
            *reinterpret_cast<float4*>(C + (size_t)r * ldc + c) = v;
        }
    }
}

// ---------------- fp16 tensor-core GEMM (value path), cp.async pipelined ----
template <int EPI, typename CT>
__global__ __launch_bounds__(256, 2) void hgemm_kernel(
    const __half* __restrict__ A, int lda,
    const __half* __restrict__ B, int ldb,
    const float* __restrict__ bias,
    const float* __restrict__ res,
    CT* __restrict__ C, int ldc, int Kd)
{
    __shared__ __half Ash[2 * 8192];   // [buf][128 rows][64] swizzled 128B rows
    __shared__ __half Bsh[2 * 8192];   // [buf][64 rows][128] swizzled 256B rows
    uint32_t sA = smem_u32(Ash), sB = smem_u32(Bsh);
    int tid = threadIdx.x, lane = tid & 31, wid = tid >> 5;
    int warp_m = wid >> 2, warp_n = wid & 3;
    int brow = blockIdx.y * 128, bcol = blockIdx.x * 128;

    float acc[4][4][4];
    #pragma unroll
    for (int mt = 0; mt < 4; mt++)
        #pragma unroll
        for (int nt = 0; nt < 4; nt++)
            #pragma unroll
            for (int r = 0; r < 4; r++) acc[mt][nt][r] = 0.f;

    auto stageA = [&](int kp, int buf) {
        #pragma unroll
        for (int it = 0; it < 4; it++) {
            int id = tid + it * 256;       // 1024 chunks = 128 rows x 8 x 16B
            int row = id >> 3, col = id & 7;
            uint32_t d = sA + buf * 16384 + row * 128 + ((col ^ (row & 7)) << 4);
            const void* s = A + (size_t)(brow + row) * lda + kp + col * 8;
            CP_ASYNC16(d, s);
        }
    };
    auto stageB = [&](int kp, int buf) {
        #pragma unroll
        for (int it = 0; it < 4; it++) {
            int id = tid + it * 256;       // 1024 chunks = 64 rows x 16 x 16B
            int k = id >> 4, c = id & 15;
            uint32_t d = sB + buf * 16384 + k * 256 + ((c ^ (k & 7)) << 4);
            const void* s = B + (size_t)(kp + k) * ldb + bcol + c * 8;
            CP_ASYNC16(d, s);
        }
    };

    uint32_t a_rel[4]; int a_rx[4];
    #pragma unroll
    for (int mt = 0; mt < 4; mt++) {
        int row = warp_m * 64 + mt * 16 + (lane & 15);
        a_rel[mt] = row * 128;
        a_rx[mt] = row & 7;
    }
    int a_ch = lane >> 4;

    uint32_t b_off[2];
    {
        int m_ = lane >> 3, r_ = lane & 7;
        int kl = (m_ & 1) * 8 + r_;
        #pragma unroll
        for (int g = 0; g < 2; g++) {
            int nchunk = warp_n * 4 + g * 2 + (m_ >> 1);
            b_off[g] = kl * 256 + ((nchunk ^ (kl & 7)) << 4);
        }
    }

    stageA(0, 0); stageB(0, 0); CP_COMMIT();

    int npan = Kd / 64;
    for (int p = 0; p < npan; p++) {
        CP_WAIT0();
        __syncthreads();
        if (p + 1 < npan) {
            stageA((p + 1) * 64, (p + 1) & 1);
            stageB((p + 1) * 64, (p + 1) & 1);
            CP_COMMIT();
        }
        uint32_t abase = sA + (p & 1) * 16384;
        uint32_t bbase = sB + (p & 1) * 16384;

        #pragma unroll
        for (int kk = 0; kk < 4; kk++) {
            uint32_t af[4][4], bf[2][4];
            #pragma unroll
            for (int mt = 0; mt < 4; mt++) {
                int ch = kk * 2 + a_ch;
                ldsm_x4(af[mt][0], af[mt][1], af[mt][2], af[mt][3],
                        abase + a_rel[mt] + ((ch ^ a_rx[mt]) << 4));
            }
            #pragma unroll
            for (int g = 0; g < 2; g++)
                ldsm_x4t(bf[g][0], bf[g][1], bf[g][2], bf[g][3],
                         bbase + kk * 4096 + b_off[g]);
            #pragma unroll
            for (int mt = 0; mt < 4; mt++) {
                mma16816h(acc[mt][0], af[mt], &bf[0][0]);
                mma16816h(acc[mt][1], af[mt], &bf[0][2]);
                mma16816h(acc[mt][2], af[mt], &bf[1][0]);
                mma16816h(acc[mt][3], af[mt], &bf[1][2]);
            }
        }
    }

    #pragma unroll
    for (int mt = 0; mt < 4; mt++) {
        #pragma unroll
        for (int rh = 0; rh < 2; rh++) {
            int r = brow + warp_m * 64 + mt * 16 + rh * 8 + (lane >> 2);
            #pragma unroll
            for (int nt = 0; nt < 4; nt++) {
                int c = bcol + warp_n * 32 + nt * 8 + 2 * (lane & 3);
                float vx = acc[mt][nt][rh * 2 + 0] + bias[c];
                float vy = acc[mt][nt][rh * 2 + 1] + bias[c + 1];
                if (EPI == EPI_BIAS_RES) {
                    float2 rv = *reinterpret_cast<const float2*>(res + (size_t)r * ldc + c);
                    vx += rv.x; vy += rv.y;
                } else if (EPI == EPI_GELU) {
                    vx = gelu_tanh(vx); vy = gelu_tanh(vy);
                }
                if (sizeof(CT) == 2) {
                    __half2 hv = __floats2half2_rn(vx, vy);
                    *reinterpret_cast<__half2*>((__half*)C + (size_t)r * ldc + c) = hv;
                } else {
                    *reinterpret_cast<float2*>((float*)C + (size_t)r * ldc + c) =
                        make_float2(vx, vy);
                }
            }
        }
    }
}

// ---------------- bf16 mma.sync score GEMM + register top-16 (R6 proven) ----
#define SC_SC 32768

__device__ __forceinline__ void stage64_async(
    uint32_t dstb, const __nv_bfloat16* __restrict__ src, int tid)
{
    #pragma unroll
    for (int it = 0; it < 4; it++) {
        int c = tid + it * 256;          // 1024 chunks = 128 rows x 8 x 16B
        int row = c >> 3, col = c & 7;
        uint32_t d = dstb + row * 128 + ((col ^ (row & 7)) << 4);
        const void* s = src + (size_t)row * DMODEL + col * 8;
        CP_ASYNC16(d, s);
    }
}

__global__ __launch_bounds__(256, 2) void score_topk_mma(
    const __nv_bfloat16* __restrict__ qb, const __nv_bfloat16* __restrict__ kb,
    uint32_t* __restrict__ part)
{
    extern __shared__ char dsm[];
    uint32_t (*Sc)[132] = (uint32_t(*)[132])(dsm + SC_SC);
    uint32_t sbase = smem_u32(dsm);

    int tid = threadIdx.x, lane = tid & 31, wid = tid >> 5;
    int warp_m = wid >> 2, warp_n = wid & 3;
    int q0 = blockIdx.y * 128;
    int c0 = blockIdx.x * CHUNK;

    uint32_t lst[16];
    #pragma unroll
    for (int r = 0; r < 16; r++) lst[r] = (lane < 16) ? 0u : 0xffffffffu;

    uint32_t a_rel[4], b_rel[2];
    int a_rx[4], b_rx[2];
    #pragma unroll
    for (int mt = 0; mt < 4; mt++) {
        int row = warp_m * 64 + mt * 16 + (lane & 15);
        a_rel[mt] = row * 128;
        a_rx[mt] = row & 7;
    }
    #pragma unroll
    for (int pr = 0; pr < 2; pr++) {
        int row = warp_n * 32 + pr * 16 + (lane & 7) + ((lane >> 4) << 3);
        b_rel[pr] = row * 128;
        b_rx[pr] = row & 7;
    }
    int a_ch = lane >> 4;
    int b_ch = (lane >> 3) & 1;

    const __nv_bfloat16* qbase = qb + (size_t)q0 * DMODEL;

    stage64_async(sbase,         qbase, tid);
    stage64_async(sbase + 16384, kb + (size_t)c0 * DMODEL, tid);
    CP_COMMIT();

    for (int kt = 0; kt < CHUNK / 128; kt++) {
        int kb0 = c0 + kt * 128;
        const __nv_bfloat16* kbase = kb + (size_t)kb0 * DMODEL;

        float acc[4][4][4];
        #pragma unroll
        for (int mt = 0; mt < 4; mt++)
            #pragma unroll
            for (int nt = 0; nt < 4; nt++)
                #pragma unroll
                for (int r = 0; r < 4; r++) acc[mt][nt][r] = 0.f;

        for (int kc = 0; kc < DMODEL / 64; kc++) {
            CP_WAIT0();
            __syncthreads();
            if (kc + 1 < DMODEL / 64) {
                uint32_t nb = sbase + ((kc + 1) & 1) * 32768;
                stage64_async(nb,         qbase + (kc + 1) * 64, tid);
                stage64_async(nb + 16384, kbase + (kc + 1) * 64, tid);
                CP_COMMIT();
            }
            uint32_t abase = sbase + (kc & 1) * 32768;
            uint32_t bbase = abase + 16384;

            #pragma unroll
            for (int kk = 0; kk < 4; kk++) {
                uint32_t af[4][4], bf[2][4];
                #pragma unroll
                for (int mt = 0; mt < 4; mt++) {
                    int ch = kk * 2 + a_ch;
                    ldsm_x4(af[mt][0], af[mt][1], af[mt][2], af[mt][3],
                            abase + a_rel[mt] + ((ch ^ a_rx[mt]) << 4));
                }
                #pragma unroll
                for (int pr = 0; pr < 2; pr++) {
                    int ch = kk * 2 + b_ch;
                    ldsm_x4(bf[pr][0], bf[pr][1], bf[pr][2], bf[pr][3],
                            bbase + b_rel[pr] + ((ch ^ b_rx[pr]) << 4));
                }
                #pragma unroll
                for (int mt = 0; mt < 4; mt++) {
                    mma16816(acc[mt][0], af[mt], &bf[0][0]);
                    mma16816(acc[mt][1], af[mt], &bf[0][2]);
                    mma16816(acc[mt][2], af[mt], &bf[1][0]);
                    mma16816(acc[mt][3], af[mt], &bf[1][2]);
                }
            }
        }

        __syncthreads();
        #pragma unroll
        for (int mt = 0; mt < 4; mt++) {
            int r = warp_m * 64 + mt * 16 + (lane >> 2);
            #pragma unroll
            for (int nt = 0; nt < 4; nt++) {
                int c = warp_n * 32 + nt * 8 + 2 * (lane & 3);
                int cl = kt * 128 + c;
                uint2 k0 = make_uint2(packkey(acc[mt][nt][0], cl),
                                      packkey(acc[mt][nt][1], cl + 1));
                uint2 k1 = make_uint2(packkey(acc[mt][nt][2], cl),
                                      packkey(acc[mt][nt][3], cl + 1));
                *reinterpret_cast<uint2*>(&Sc[r][c])     = k0;
                *reinterpret_cast<uint2*>(&Sc[r + 8][c]) = k1;
            }
        }
        __syncthreads();

        if (kt + 1 < CHUNK / 128) {
            stage64_async(sbase,         qbase, tid);
            stage64_async(sbase + 16384, kb + (size_t)(kb0 + 128) * DMODEL, tid);
            CP_COMMIT();
        }

        #pragma unroll
        for (int r = 0; r < 16; r++) {
            int row = wid * 16 + r;
            uint4 kv = *reinterpret_cast<const uint4*>(&Sc[row][lane * 4]);
            uint32_t thr = __shfl_sync(0xffffffffu, lst[r], 15);
            bool c = (kv.x > thr) | (kv.y > thr) | (kv.z > thr) | (kv.w > thr);
            unsigned m = __ballot_sync(0xffffffffu, c);
            while (m) {
                int src = __ffs(m) - 1; m &= m - 1;
                uint32_t k0 = __shfl_sync(0xffffffffu, kv.x, src);
                uint32_t k1 = __shfl_sync(0xffffffffu, kv.y, src);
                uint32_t k2 = __shfl_sync(0xffffffffu, kv.z, src);
                uint32_t k3 = __shfl_sync(0xffffffffu, kv.w, src);
                thr = __shfl_sync(0xffffffffu, lst[r], 15);
                if (k0 > thr) { ins16(lst[r], k0, lane); thr = __shfl_sync(0xffffffffu, lst[r], 15); }
                if (k1 > thr) { ins16(lst[r], k1, lane); thr = __shfl_sync(0xffffffffu, lst[r], 15); }
                if (k2 > thr) { ins16(lst[r], k2, lane); thr = __shfl_sync(0xffffffffu, lst[r], 15); }
                if (k3 > thr) { ins16(lst[r], k3, lane); }
            }
        }
        __syncthreads();
    }

    if (lane < 16) {
        #pragma unroll
        for (int r = 0; r < 16; r++) {
            int row = q0 + wid * 16 + r;
            part[((size_t)row * NCH + blockIdx.x) * KSEL + lane] = lst[r];
        }
    }
}

// ---------------- merge 128 packed candidates/row -> top-32 -----------------
__global__ __launch_bounds__(256) void merge32_kernel(
    const uint32_t* __restrict__ part, int* __restrict__ cand)
{
    int lane = threadIdx.x & 31;
    int row  = blockIdx.x * 8 + (threadIdx.x >> 5);
    unsigned long long mk[4];
    #pragma unroll
    for (int j = 0; j < 4; j++) {
        int e = lane + 32 * j;
        uint32_t key = part[(size_t)row * 128 + e];
        int gid = (e >> 4) * CHUNK + 4095 - (int)(key & 0xfffu);
        mk[j] = ((unsigned long long)(key >> 16) << 32) | (uint32_t)(0xffffffffu - gid);
    }
    for (int t = 0; t < NCAND; t++) {
        unsigned long long best = mk[0];
        #pragma unroll
        for (int j = 1; j < 4; j++) if (mk[j] > best) best = mk[j];
        #pragma unroll
        for (int o = 16; o > 0; o >>= 1) {
            unsigned long long ob = __shfl_xor_sync(0xffffffffu, best, o);
            if (ob > best) best = ob;
        }
        if (lane == 0)
            cand[row * NCAND + t] = (int)(0xffffffffu - (uint32_t)best);
        #pragma unroll
        for (int j = 0; j < 4; j++) if (mk[j] == best) mk[j] = 0;
    }
}

// ---------------- exact fp32 rescore of 32 candidates -> final top-16 -------
__global__ __launch_bounds__(256) void rescore_kernel(
    const float* __restrict__ q, const float* __restrict__ dbk,
    const int* __restrict__ cand, int* __restrict__ topk)
{
    __shared__ float sq[DMODEL];
    __shared__ float ss[NCAND];
    __shared__ int   sid[NCAND];
    int t = blockIdx.x, tid = threadIdx.x;
    int w = tid >> 5, lane = tid & 31;
    sq[tid]       = q[(size_t)t * DMODEL + tid];
    sq[tid + 256] = q[(size_t)t * DMODEL + tid + 256];
    sq[tid + 512] = q[(size_t)t * DMODEL + tid + 512];
    if (tid < NCAND) sid[tid] = cand[t * NCAND + tid];
    __syncthreads();

    for (int cc = w; cc < NCAND; cc += 8) {
        const float* kr = dbk + (size_t)sid[cc] * DMODEL;
        float p = 0.f;
        #pragma unroll
        for (int j = 0; j < DMODEL / 32; j++)
            p += sq[lane + 32 * j] * kr[lane + 32 * j];
        #pragma unroll
        for (int o = 16; o > 0; o >>= 1) p += __shfl_xor_sync(0xffffffffu, p, o);
        if (lane == 0) ss[cc] = p;
    }
    __syncthreads();

    if (w == 0) {
        float s = ss[lane];
        int  id = sid[lane];
        for (int it = 0; it < KSEL; it++) {
            float bs = s; int bid = id;
            #pragma unroll
            for (int o = 16; o > 0; o >>= 1) {
                float os = __shfl_xor_sync(0xffffffffu, bs, o);
                int   oi = __shfl_xor_sync(0xffffffffu, bid, o);
                if (better(os, oi, bs, bid)) { bs = os; bid = oi; }
            }
            if (lane == 0) topk[t * KSEL + it] = bid;
            if (id == bid) { s = -CUDART_INF_F; id = 0x7fffffff; }
        }
    }
}

// ---------------- per-token memory attention (fp16 output) ------------------
__global__ __launch_bounds__(384) void attn_kernel(
    const float* __restrict__ q, const float* __restrict__ dbk,
    const float* __restrict__ dbv, const int* __restrict__ topk,
    __half* __restrict__ out)
{
    __shared__ float sq[DMODEL];
    __shared__ int   sidx[KSEL];
    __shared__ float saw[NH][KSEL];
    int t = blockIdx.x;
    int tid = threadIdx.x, lane = tid & 31, w = tid >> 5;
    sq[tid]       = q[(size_t)t * DMODEL + tid];
    sq[tid + 384] = q[(size_t)t * DMODEL + tid + 384];
    if (tid < KSEL) sidx[tid] = topk[t * KSEL + tid];
    __syncthreads();

    float q1 = sq[w * HD + lane], q2 = sq[w * HD + lane + 32];
    for (int m = 0; m < KSEL; m++) {
        const float* kr = dbk + (size_t)sidx[m] * DMODEL + w * HD;
        float p = q1 * kr[lane] + q2 * kr[lane + 32];
        #pragma unroll
        for (int o = 16; o > 0; o >>= 1) p += __shfl_xor_sync(0xffffffffu, p, o);
        if (lane == 0) saw[w][m] = p * 0.125f;
    }
    __syncwarp();
    {
        float x = (lane < KSEL) ? saw[w][lane] : -CUDART_INF_F;
        float mx = x;
        #pragma unroll
        for (int o = 16; o > 0; o >>= 1) mx = fmaxf(mx, __shfl_xor_sync(0xffffffffu, mx, o));
        float e = (lane < KSEL) ? expf(x - mx) : 0.f;
        float se = e;
        #pragma unroll
        for (int o = 16; o > 0; o >>= 1) se += __shfl_xor_sync(0xffffffffu, se, o);
        if (lane < KSEL) saw[w][lane] = e / se;
    }
    __syncwarp();
    float a1 = 0.f, a2 = 0.f;
    for (int m = 0; m < KSEL; m++) {
        float aw = saw[w][m];
        const float* vr = dbv + (size_t)sidx[m] * DMODEL + w * HD;
        a1 += aw * vr[lane]; a2 += aw * vr[lane + 32];
    }
    out[(size_t)t * DMODEL + w * HD + lane]      = __float2half_rn(a1);
    out[(size_t)t * DMODEL + w * HD + lane + 32] = __float2half_rn(a2);
}

// ---------------- launch -----------------------------------------------------
extern "C" void kernel_launch(void* const* d_in, const int* in_sizes, int n_in,
                              void* d_out, int out_size)
{
    const float* prev   = (const float*)d_in[0];
    const float* dbk    = (const float*)d_in[1];
    const float* dbv    = (const float*)d_in[2];
    const float* ln1g   = (const float*)d_in[3];
    const float* ln1b   = (const float*)d_in[4];
    const float* cattnw = (const float*)d_in[5];
    const float* cattnb = (const float*)d_in[6];
    const float* cprojw = (const float*)d_in[7];
    const float* cprojb = (const float*)d_in[8];
    const float* ln2g   = (const float*)d_in[9];
    const float* ln2b   = (const float*)d_in[10];
    const float* fcw    = (const float*)d_in[11];
    const float* fcb    = (const float*)d_in[12];
    const float* projw  = (const float*)d_in[13];
    const float* projb  = (const float*)d_in[14];
    float* out = (float*)d_out;

    float *p_ln, *p_q, *p_h;
    __half *p_attnh, *p_lnh, *p_ff1h, *p_wh;
    __nv_bfloat16 *p_qb, *p_kb;
    uint32_t *p_part;
    int *p_cand, *p_topk;
    cudaGetSymbolAddress((void**)&p_ln,    g_ln);
    cudaGetSymbolAddress((void**)&p_q,     g_q);
    cudaGetSymbolAddress((void**)&p_h,     g_h);
    cudaGetSymbolAddress((void**)&p_attnh, g_attnh);
    cudaGetSymbolAddress((void**)&p_lnh,   g_lnh);
    cudaGetSymbolAddress((void**)&p_ff1h,  g_ff1h);
    cudaGetSymbolAddress((void**)&p_wh,    g_wh);
    cudaGetSymbolAddress((void**)&p_qb,    g_qb);
    cudaGetSymbolAddress((void**)&p_kb,    g_kb);
    cudaGetSymbolAddress((void**)&p_part,  g_part);
    cudaGetSymbolAddress((void**)&p_cand,  g_cand);
    cudaGetSymbolAddress((void**)&p_topk,  g_topk);

    const __half* cprojw_h = p_wh + W_CPROJ_OFF;
    const __half* fcw_h    = p_wh + W_FC_OFF;
    const __half* projw_h  = p_wh + W_PROJ_OFF;

    // 0. one-pass fp16 conversion of value-path weights
    w2h_kernel<<<(W_TOTAL / 4) / 256, 256>>>(cprojw, fcw, projw, p_wh);

    // 1. LN1 (exact fp32 — feeds selection-critical q path)
    ln_kernel<<<NTOK, 256>>>(prev, ln1g, ln1b, p_ln);

    // 2. q = LN1(x) @ c_attn_w[:, :768] + bias  (exact fp32 via f32x2 FMA)
    sgemm_kernel<EPI_BIAS><<<dim3(DMODEL / 128, NTOK / 128), 256>>>(
        p_ln, DMODEL, cattnw, 3 * DMODEL, cattnb, nullptr, p_q, DMODEL, DMODEL);

    // 3. bf16 conversions (single launch)
    {
        int nq4 = NTOK * DMODEL / 4;
        int nk4 = MDB * DMODEL / 4;
        f2bf2_kernel<<<(nq4 + nk4) / 256, 256>>>(p_q, p_qb, dbk, p_kb, nq4);
    }

    // 4. bf16 mma.sync score GEMM + register top-16 (R6 config)
    int smem = 32768 + 128 * 132 * 4;  // 100352 B
    cudaFuncSetAttribute(score_topk_mma,
                         cudaFuncAttributeMaxDynamicSharedMemorySize, smem);
    score_topk_mma<<<dim3(NCH, NTOK / 128), 256, smem>>>(p_qb, p_kb, p_part);

    // 5. merge 128 packed candidates -> top-32 per token
    merge32_kernel<<<NTOK / 8, 256>>>(p_part, p_cand);

    // 6. exact fp32 rescore of top-32 -> final top-16 (jax tie-break)
    rescore_kernel<<<NTOK, 256>>>(p_q, dbk, p_cand, p_topk);

    // 7. per-token per-head softmax attention (fp16 output)
    attn_kernel<<<NTOK, 384>>>(p_q, dbk, dbv, p_topk, p_attnh);

    // 8. h = attn @ c_proj_w + bias + residual   (fp16 tensor cores, fp32 out)
    hgemm_kernel<EPI_BIAS_RES, float><<<dim3(DMODEL / 128, NTOK / 128), 256>>>(
        p_attnh, DMODEL, cprojw_h, DMODEL, cprojb, prev, p_h, DMODEL, DMODEL);

    // 9. LN2 (fp16 output — feeds fc GEMM only)
    lnh_kernel<<<NTOK, 256>>>(p_h, ln2g, ln2b, p_lnh);

    // 10. ff1 = gelu(LN2(h) @ fc_w + fc_b)       (fp16; half output)
    hgemm_kernel<EPI_GELU, __half><<<dim3(DFF / 128, NTOK / 128), 256>>>(
        p_lnh, DMODEL, fcw_h, DFF, fcb, nullptr, p_ff1h, DFF, DMODEL);

    // 11. out = ff1 @ proj_w + proj_b + h        (fp16, fp32 out)
    hgemm_kernel<EPI_BIAS_RES, float><<<dim3(DMODEL / 128, NTOK / 128), 256>>>(
        p_ff1h, DFF, projw_h, DMODEL, projb, p_h, out, DMODEL, DFF);
}